// round 5
// baseline (speedup 1.0000x reference)
#include <cuda_runtime.h>
#include <cuda_bf16.h>

// 2-layer GCN: out = Ahat(relu(Ahat(x@W1)+b1) @ W2) + b2
// Ahat = D^-1/2 (A+I) D^-1/2. Factored: rows of h scaled by dis[src] in the
// GEMM epilogue, aggregation is a pure segment-sum, output scaled by dis[dst].
// Edge array stores src only (4B/edge).

#define NN 50000
#define NE 800000
#define ET (NN + NE)
#define FIN 128
#define D1  128
#define NCLS 64

// ---- device scratch (static, no allocation) ----
__device__ float g_h1[NN * D1];      // dis[r] * (x @ W1)[r]
__device__ float g_a1[NN * D1];      // relu(dis[d]*sum + b1)
__device__ float g_h2[NN * NCLS];    // dis[r] * (a1 @ W2)[r]
__device__ int   g_deg[NN];
__device__ float g_dis[NN];
__device__ int   g_off[NN + 1];
__device__ int   g_cnt[NN];
__device__ int   g_src[ET];
__device__ int   g_is64;

// ---- packed f32x2 helpers ----
__device__ __forceinline__ unsigned long long pack2(float lo, float hi) {
    unsigned long long r;
    asm("mov.b64 %0, {%1, %2};" : "=l"(r) : "f"(lo), "f"(hi));
    return r;
}
__device__ __forceinline__ void fma2(unsigned long long& d,
                                     unsigned long long a,
                                     unsigned long long b) {
    asm("fma.rn.f32x2 %0, %1, %2, %3;" : "=l"(d) : "l"(a), "l"(b), "l"(d));
}
__device__ __forceinline__ float lo32(unsigned long long v) {
    return __uint_as_float((unsigned)v);
}
__device__ __forceinline__ float hi32(unsigned long long v) {
    return __uint_as_float((unsigned)(v >> 32));
}

// ---------------------------------------------------------------------------
__global__ void init_detect_kernel(const int* __restrict__ raw) {
    int i = blockIdx.x * blockDim.x + threadIdx.x;
    if (i < NN) { g_deg[i] = 0; g_cnt[i] = 0; }
    if (blockIdx.x == 0) {
        __shared__ int nz;
        if (threadIdx.x == 0) nz = 0;
        __syncthreads();
        for (int k = threadIdx.x; k < 512; k += blockDim.x)
            if (raw[2 * k + 1] != 0) atomicOr(&nz, 1);
        __syncthreads();
        if (threadIdx.x == 0) g_is64 = (nz == 0) ? 1 : 0;
    }
}

__device__ __forceinline__ int edge_at(const void* raw, int idx) {
    if (g_is64) return (int)((const long long*)raw)[idx];
    return ((const int*)raw)[idx];
}

__global__ void degree_kernel(const void* __restrict__ ei) {
    int e = blockIdx.x * blockDim.x + threadIdx.x;
    if (e < NE) atomicAdd(&g_deg[edge_at(ei, NE + e)], 1);
}

// single block, 1024 thr: each owns a 49-elem chunk. deg+1, dis=rsqrt,
// exclusive scan -> g_off.
__global__ void __launch_bounds__(1024) scan_dis_kernel() {
    const int CHUNK = 49;                      // 1024*49 >= NN
    __shared__ int tsum[1024];
    __shared__ int wsum[32];
    int tid = threadIdx.x, lane = tid & 31, w = tid >> 5;
    int base = tid * CHUNK;

    int s = 0;
    for (int j = 0; j < CHUNK; j++) {
        int i = base + j;
        if (i < NN) {
            int v = g_deg[i] + 1;              // +1 self loop
            g_dis[i] = rsqrtf((float)v);
            s += v;
        }
    }
    tsum[tid] = s;
    __syncthreads();

    int x = s;
    #pragma unroll
    for (int d = 1; d < 32; d <<= 1) {
        int t = __shfl_up_sync(0xffffffffu, x, d);
        if (lane >= d) x += t;
    }
    if (lane == 31) wsum[w] = x;
    __syncthreads();
    if (w == 0) {
        int y = wsum[lane];
        #pragma unroll
        for (int d = 1; d < 32; d <<= 1) {
            int t = __shfl_up_sync(0xffffffffu, y, d);
            if (lane >= d) y += t;
        }
        wsum[lane] = y;
    }
    __syncthreads();

    int run = x - s + (w > 0 ? wsum[w - 1] : 0);
    for (int j = 0; j < CHUNK; j++) {
        int i = base + j;
        if (i < NN) {
            g_off[i] = run;
            run += g_deg[i] + 1;
        }
    }
    if (tid == 1023) g_off[NN] = run;          // == ET
}

__global__ void scatter_kernel(const void* __restrict__ ei) {
    int e = blockIdx.x * blockDim.x + threadIdx.x;
    if (e >= ET) return;
    int s, d;
    if (e < NE) { s = edge_at(ei, e); d = edge_at(ei, NE + e); }
    else        { s = d = e - NE; }
    int pos = g_off[d] + atomicAdd(&g_cnt[d], 1);
    g_src[pos] = s;
}

// ---------------------------------------------------------------------------
// fp32 SGEMM (f32x2 mainloop), K=128, BM=128, BK=16, 256 threads.
// Epilogue scales output row r by g_dis[r].
__global__ void __launch_bounds__(256) sgemm1(
    const float* __restrict__ A, const float* __restrict__ B, int M)
{
    constexpr int BM = 128, BN = 128, BK = 16, K = 128, TM = 8, TN = 8;
    __shared__ float As[BK][BM];
    __shared__ float Bs[BK][BN];

    const int tid = threadIdx.x;
    const int block_row = blockIdx.x * BM;
    const int tx = tid % (BN / TN);
    const int ty = tid / (BN / TN);

    unsigned long long acc2[TM][TN / 2];
    #pragma unroll
    for (int i = 0; i < TM; i++)
        #pragma unroll
        for (int j = 0; j < TN / 2; j++) acc2[i][j] = 0ull;

    const int a_r = tid / 4;
    const int a_c = (tid % 4) * 4;
    const int b_r = tid / (BN / 4);
    const int b_c = (tid % (BN / 4)) * 4;

    for (int k0 = 0; k0 < K; k0 += BK) {
        #pragma unroll
        for (int it = 0; it < 2; it++) {
            int r = a_r + it * 64;
            int grow = block_row + r;
            float4 v = make_float4(0.f, 0.f, 0.f, 0.f);
            if (grow < M) v = *(const float4*)&A[(size_t)grow * K + k0 + a_c];
            As[a_c + 0][r] = v.x;
            As[a_c + 1][r] = v.y;
            As[a_c + 2][r] = v.z;
            As[a_c + 3][r] = v.w;
        }
        #pragma unroll
        for (int it = 0; it < 2; it++) {
            int r = b_r + it * 8;
            *(float4*)&Bs[r][b_c] = *(const float4*)&B[(size_t)(k0 + r) * BN + b_c];
        }
        __syncthreads();

        #pragma unroll
        for (int k = 0; k < BK; k++) {
            unsigned long long ra2[TM], rb2[TN / 2];
            #pragma unroll
            for (int i = 0; i < TM; i++) {
                float a = As[k][ty * TM + i];
                ra2[i] = pack2(a, a);
            }
            #pragma unroll
            for (int j = 0; j < TN / 2; j++)
                rb2[j] = *(const unsigned long long*)&Bs[k][tx * TN + 2 * j];
            #pragma unroll
            for (int i = 0; i < TM; i++)
                #pragma unroll
                for (int j = 0; j < TN / 2; j++)
                    fma2(acc2[i][j], ra2[i], rb2[j]);
        }
        __syncthreads();
    }

    #pragma unroll
    for (int i = 0; i < TM; i++) {
        int grow = block_row + ty * TM + i;
        if (grow < M) {
            float dsc = g_dis[grow];
            #pragma unroll
            for (int j = 0; j < TN / 2; j += 2) {
                float4 v = make_float4(dsc * lo32(acc2[i][j]),
                                       dsc * hi32(acc2[i][j]),
                                       dsc * lo32(acc2[i][j + 1]),
                                       dsc * hi32(acc2[i][j + 1]));
                *(float4*)&g_h1[(size_t)grow * BN + tx * TN + 2 * j] = v;
            }
        }
    }
}

__global__ void __launch_bounds__(256) sgemm2(
    const float* __restrict__ B, int M)
{
    constexpr int BM = 128, BN = 64, BK = 16, K = 128, TM = 8, TN = 4;
    __shared__ float As[BK][BM];
    __shared__ float Bs[BK][BN];

    const int tid = threadIdx.x;
    const int block_row = blockIdx.x * BM;
    const int tx = tid % (BN / TN);
    const int ty = tid / (BN / TN);

    unsigned long long acc2[TM][TN / 2];
    #pragma unroll
    for (int i = 0; i < TM; i++)
        #pragma unroll
        for (int j = 0; j < TN / 2; j++) acc2[i][j] = 0ull;

    const int a_r = tid / 4;
    const int a_c = (tid % 4) * 4;
    const int b_r = tid / (BN / 4);
    const int b_c = (tid % (BN / 4)) * 4;

    for (int k0 = 0; k0 < K; k0 += BK) {
        #pragma unroll
        for (int it = 0; it < 2; it++) {
            int r = a_r + it * 64;
            int grow = block_row + r;
            float4 v = make_float4(0.f, 0.f, 0.f, 0.f);
            if (grow < M) v = *(const float4*)&g_a1[(size_t)grow * K + k0 + a_c];
            As[a_c + 0][r] = v.x;
            As[a_c + 1][r] = v.y;
            As[a_c + 2][r] = v.z;
            As[a_c + 3][r] = v.w;
        }
        {
            int r = b_r;
            *(float4*)&Bs[r][b_c] = *(const float4*)&B[(size_t)(k0 + r) * BN + b_c];
        }
        __syncthreads();

        #pragma unroll
        for (int k = 0; k < BK; k++) {
            unsigned long long ra2[TM], rb2[TN / 2];
            #pragma unroll
            for (int i = 0; i < TM; i++) {
                float a = As[k][ty * TM + i];
                ra2[i] = pack2(a, a);
            }
            #pragma unroll
            for (int j = 0; j < TN / 2; j++)
                rb2[j] = *(const unsigned long long*)&Bs[k][tx * TN + 2 * j];
            #pragma unroll
            for (int i = 0; i < TM; i++)
                #pragma unroll
                for (int j = 0; j < TN / 2; j++)
                    fma2(acc2[i][j], ra2[i], rb2[j]);
        }
        __syncthreads();
    }

    #pragma unroll
    for (int i = 0; i < TM; i++) {
        int grow = block_row + ty * TM + i;
        if (grow < M) {
            float dsc = g_dis[grow];
            float4 v = make_float4(dsc * lo32(acc2[i][0]), dsc * hi32(acc2[i][0]),
                                   dsc * lo32(acc2[i][1]), dsc * hi32(acc2[i][1]));
            *(float4*)&g_h2[(size_t)grow * BN + tx * TN] = v;
        }
    }
}

// ---------------------------------------------------------------------------
// Segment sum: warp per node, pure float4/float2 adds, dis[dst] in epilogue.
__global__ void __launch_bounds__(256) agg128_relu(
    const float* __restrict__ bias)
{
    int gw = (blockIdx.x * blockDim.x + threadIdx.x) >> 5;
    int lane = threadIdx.x & 31;
    if (gw >= NN) return;
    int beg = g_off[gw], end = g_off[gw + 1];
    int c4 = lane * 4;

    float4 acc = make_float4(0.f, 0.f, 0.f, 0.f);
    int idx = beg;
    for (; idx + 4 <= end; idx += 4) {
        int s0 = g_src[idx + 0];
        int s1 = g_src[idx + 1];
        int s2 = g_src[idx + 2];
        int s3 = g_src[idx + 3];
        float4 v0 = *(const float4*)(g_h1 + (size_t)s0 * 128 + c4);
        float4 v1 = *(const float4*)(g_h1 + (size_t)s1 * 128 + c4);
        float4 v2 = *(const float4*)(g_h1 + (size_t)s2 * 128 + c4);
        float4 v3 = *(const float4*)(g_h1 + (size_t)s3 * 128 + c4);
        acc.x += v0.x + v1.x + v2.x + v3.x;
        acc.y += v0.y + v1.y + v2.y + v3.y;
        acc.z += v0.z + v1.z + v2.z + v3.z;
        acc.w += v0.w + v1.w + v2.w + v3.w;
    }
    for (; idx < end; idx++) {
        int s = g_src[idx];
        float4 v = *(const float4*)(g_h1 + (size_t)s * 128 + c4);
        acc.x += v.x; acc.y += v.y; acc.z += v.z; acc.w += v.w;
    }
    float dd = g_dis[gw];
    float4 bb = *(const float4*)(bias + c4);
    acc.x = fmaxf(fmaf(dd, acc.x, bb.x), 0.f);
    acc.y = fmaxf(fmaf(dd, acc.y, bb.y), 0.f);
    acc.z = fmaxf(fmaf(dd, acc.z, bb.z), 0.f);
    acc.w = fmaxf(fmaf(dd, acc.w, bb.w), 0.f);
    *(float4*)(g_a1 + (size_t)gw * 128 + c4) = acc;
}

__global__ void __launch_bounds__(256) agg64_out(
    const float* __restrict__ bias, float* __restrict__ OUT)
{
    int gw = (blockIdx.x * blockDim.x + threadIdx.x) >> 5;
    int lane = threadIdx.x & 31;
    if (gw >= NN) return;
    int beg = g_off[gw], end = g_off[gw + 1];
    int c2 = lane * 2;

    float2 acc = make_float2(0.f, 0.f);
    int idx = beg;
    for (; idx + 4 <= end; idx += 4) {
        int s0 = g_src[idx + 0];
        int s1 = g_src[idx + 1];
        int s2 = g_src[idx + 2];
        int s3 = g_src[idx + 3];
        float2 v0 = *(const float2*)(g_h2 + (size_t)s0 * 64 + c2);
        float2 v1 = *(const float2*)(g_h2 + (size_t)s1 * 64 + c2);
        float2 v2 = *(const float2*)(g_h2 + (size_t)s2 * 64 + c2);
        float2 v3 = *(const float2*)(g_h2 + (size_t)s3 * 64 + c2);
        acc.x += v0.x + v1.x + v2.x + v3.x;
        acc.y += v0.y + v1.y + v2.y + v3.y;
    }
    for (; idx < end; idx++) {
        int s = g_src[idx];
        float2 v = *(const float2*)(g_h2 + (size_t)s * 64 + c2);
        acc.x += v.x; acc.y += v.y;
    }
    float dd = g_dis[gw];
    float2 bb = *(const float2*)(bias + c2);
    acc.x = fmaf(dd, acc.x, bb.x);
    acc.y = fmaf(dd, acc.y, bb.y);
    *(float2*)(OUT + (size_t)gw * 64 + c2) = acc;
}

// ---------------------------------------------------------------------------
extern "C" void kernel_launch(void* const* d_in, const int* in_sizes, int n_in,
                              void* d_out, int out_size) {
    const float* x  = (const float*)d_in[0];
    const void*  ei = d_in[1];
    const float* W1 = (const float*)d_in[2];
    const float* b1 = (const float*)d_in[3];
    const float* W2 = (const float*)d_in[4];
    const float* b2 = (const float*)d_in[5];
    float*       out = (float*)d_out;

    const int TB = 256;
    init_detect_kernel<<<(NN + TB - 1) / TB, TB>>>((const int*)ei);
    degree_kernel<<<(NE + TB - 1) / TB, TB>>>(ei);
    scan_dis_kernel<<<1, 1024>>>();
    scatter_kernel<<<(ET + TB - 1) / TB, TB>>>(ei);

    sgemm1<<<(NN + 127) / 128, 256>>>(x, W1, NN);
    agg128_relu<<<(NN * 32 + TB - 1) / TB, TB>>>(b1);

    sgemm2<<<(NN + 127) / 128, 256>>>(W2, NN);
    agg64_out<<<(NN * 32 + TB - 1) / TB, TB>>>(b2, out);
}

// round 6
// speedup vs baseline: 1.2741x; 1.2741x over previous
#include <cuda_runtime.h>
#include <cuda_bf16.h>

// 2-layer GCN. Ahat = D^-1/2 (A+I) D^-1/2, factored as:
//   agg(h)[d] = dis[d] * sum_{s in N(d)} dis[s] * h[s]
// Pure GEMMs (stream-overlapped with graph prep), segment-sum aggregation
// over dst-sorted edges (4B src per edge).

#define NN 50000
#define NE 800000
#define ET (NN + NE)
#define FIN 128
#define D1  128
#define NCLS 64

// ---- device scratch (static, no allocation) ----
__device__ float g_h1[NN * D1];
__device__ float g_a1[NN * D1];
__device__ float g_h2[NN * NCLS];
__device__ int   g_deg[NN];      // zeroed by tail of previous launch
__device__ float g_dis[NN];
__device__ int   g_off[NN + 1];
__device__ int   g_cnt[NN];      // zeroed by tail of previous launch
__device__ int   g_src[ET];
__device__ int   g_is64;

// ---- packed f32x2 helpers ----
__device__ __forceinline__ unsigned long long pack2(float lo, float hi) {
    unsigned long long r;
    asm("mov.b64 %0, {%1, %2};" : "=l"(r) : "f"(lo), "f"(hi));
    return r;
}
__device__ __forceinline__ void fma2(unsigned long long& d,
                                     unsigned long long a,
                                     unsigned long long b) {
    asm("fma.rn.f32x2 %0, %1, %2, %3;" : "=l"(d) : "l"(a), "l"(b), "l"(d));
}
__device__ __forceinline__ float lo32(unsigned long long v) {
    return __uint_as_float((unsigned)v);
}
__device__ __forceinline__ float hi32(unsigned long long v) {
    return __uint_as_float((unsigned)(v >> 32));
}

// ---------------------------------------------------------------------------
// edge dtype probe (JAX silently demotes int64 -> int32 without x64 flag)
__global__ void detect_kernel(const int* __restrict__ raw) {
    __shared__ int nz;
    if (threadIdx.x == 0) nz = 0;
    __syncthreads();
    for (int k = threadIdx.x; k < 512; k += blockDim.x)
        if (raw[2 * k + 1] != 0) atomicOr(&nz, 1);
    __syncthreads();
    if (threadIdx.x == 0) g_is64 = (nz == 0) ? 1 : 0;
}

__device__ __forceinline__ int edge_at(const void* raw, int idx) {
    if (g_is64) return (int)((const long long*)raw)[idx];
    return ((const int*)raw)[idx];
}

__global__ void degree_kernel(const void* __restrict__ ei) {
    int e = blockIdx.x * blockDim.x + threadIdx.x;
    if (e < NE) atomicAdd(&g_deg[edge_at(ei, NE + e)], 1);
}

// single-block coalesced scan: d=deg+1, dis=rsqrt(d), exclusive scan -> g_off
__global__ void __launch_bounds__(1024) scan_dis_kernel() {
    __shared__ int warp_sums[32];
    __shared__ int carry;
    int tid = threadIdx.x, lane = tid & 31, w = tid >> 5;
    if (tid == 0) carry = 0;
    __syncthreads();
    for (int base = 0; base < NN; base += 1024) {
        int i = base + tid;
        int v = 0;
        if (i < NN) {
            v = g_deg[i] + 1;              // +1 self loop
            g_dis[i] = rsqrtf((float)v);
        }
        int x = v;
        #pragma unroll
        for (int d = 1; d < 32; d <<= 1) {
            int t = __shfl_up_sync(0xffffffffu, x, d);
            if (lane >= d) x += t;
        }
        if (lane == 31) warp_sums[w] = x;
        __syncthreads();
        if (w == 0) {
            int y = warp_sums[lane];
            #pragma unroll
            for (int d = 1; d < 32; d <<= 1) {
                int t = __shfl_up_sync(0xffffffffu, y, d);
                if (lane >= d) y += t;
            }
            warp_sums[lane] = y;
        }
        __syncthreads();
        int excl = x - v + (w > 0 ? warp_sums[w - 1] : 0) + carry;
        if (i < NN) g_off[i] = excl;
        __syncthreads();
        if (tid == 0) carry += warp_sums[31];
        __syncthreads();
    }
    if (threadIdx.x == 0) g_off[NN] = carry;   // == ET
}

__global__ void scatter_kernel(const void* __restrict__ ei) {
    int e = blockIdx.x * blockDim.x + threadIdx.x;
    if (e >= ET) return;
    int s, d;
    if (e < NE) { s = edge_at(ei, e); d = edge_at(ei, NE + e); }
    else        { s = d = e - NE; }
    int pos = g_off[d] + atomicAdd(&g_cnt[d], 1);
    g_src[pos] = s;
}

// ---------------------------------------------------------------------------
// Pure fp32 SGEMM (f32x2 mainloop), K=128, BM=128, BK=16, 256 threads.
__global__ void __launch_bounds__(256) sgemm1(
    const float* __restrict__ A, const float* __restrict__ B, int M)
{
    constexpr int BM = 128, BN = 128, BK = 16, K = 128, TM = 8, TN = 8;
    __shared__ float As[BK][BM];
    __shared__ float Bs[BK][BN];

    const int tid = threadIdx.x;
    const int block_row = blockIdx.x * BM;
    const int tx = tid % (BN / TN);
    const int ty = tid / (BN / TN);

    unsigned long long acc2[TM][TN / 2];
    #pragma unroll
    for (int i = 0; i < TM; i++)
        #pragma unroll
        for (int j = 0; j < TN / 2; j++) acc2[i][j] = 0ull;

    const int a_r = tid / 4;
    const int a_c = (tid % 4) * 4;
    const int b_r = tid / (BN / 4);
    const int b_c = (tid % (BN / 4)) * 4;

    for (int k0 = 0; k0 < K; k0 += BK) {
        #pragma unroll
        for (int it = 0; it < 2; it++) {
            int r = a_r + it * 64;
            int grow = block_row + r;
            float4 v = make_float4(0.f, 0.f, 0.f, 0.f);
            if (grow < M) v = *(const float4*)&A[(size_t)grow * K + k0 + a_c];
            As[a_c + 0][r] = v.x;
            As[a_c + 1][r] = v.y;
            As[a_c + 2][r] = v.z;
            As[a_c + 3][r] = v.w;
        }
        #pragma unroll
        for (int it = 0; it < 2; it++) {
            int r = b_r + it * 8;
            *(float4*)&Bs[r][b_c] = *(const float4*)&B[(size_t)(k0 + r) * BN + b_c];
        }
        __syncthreads();

        #pragma unroll
        for (int k = 0; k < BK; k++) {
            unsigned long long ra2[TM], rb2[TN / 2];
            #pragma unroll
            for (int i = 0; i < TM; i++) {
                float a = As[k][ty * TM + i];
                ra2[i] = pack2(a, a);
            }
            #pragma unroll
            for (int j = 0; j < TN / 2; j++)
                rb2[j] = *(const unsigned long long*)&Bs[k][tx * TN + 2 * j];
            #pragma unroll
            for (int i = 0; i < TM; i++)
                #pragma unroll
                for (int j = 0; j < TN / 2; j++)
                    fma2(acc2[i][j], ra2[i], rb2[j]);
        }
        __syncthreads();
    }

    #pragma unroll
    for (int i = 0; i < TM; i++) {
        int grow = block_row + ty * TM + i;
        if (grow < M) {
            #pragma unroll
            for (int j = 0; j < TN / 2; j += 2) {
                float4 v = make_float4(lo32(acc2[i][j]), hi32(acc2[i][j]),
                                       lo32(acc2[i][j + 1]), hi32(acc2[i][j + 1]));
                *(float4*)&g_h1[(size_t)grow * BN + tx * TN + 2 * j] = v;
            }
        }
    }
}

__global__ void __launch_bounds__(256) sgemm2(
    const float* __restrict__ B, int M)
{
    constexpr int BM = 128, BN = 64, BK = 16, K = 128, TM = 8, TN = 4;
    __shared__ float As[BK][BM];
    __shared__ float Bs[BK][BN];

    const int tid = threadIdx.x;
    const int block_row = blockIdx.x * BM;
    const int tx = tid % (BN / TN);
    const int ty = tid / (BN / TN);

    unsigned long long acc2[TM][TN / 2];
    #pragma unroll
    for (int i = 0; i < TM; i++)
        #pragma unroll
        for (int j = 0; j < TN / 2; j++) acc2[i][j] = 0ull;

    const int a_r = tid / 4;
    const int a_c = (tid % 4) * 4;
    const int b_r = tid / (BN / 4);
    const int b_c = (tid % (BN / 4)) * 4;

    for (int k0 = 0; k0 < K; k0 += BK) {
        #pragma unroll
        for (int it = 0; it < 2; it++) {
            int r = a_r + it * 64;
            int grow = block_row + r;
            float4 v = make_float4(0.f, 0.f, 0.f, 0.f);
            if (grow < M) v = *(const float4*)&g_a1[(size_t)grow * K + k0 + a_c];
            As[a_c + 0][r] = v.x;
            As[a_c + 1][r] = v.y;
            As[a_c + 2][r] = v.z;
            As[a_c + 3][r] = v.w;
        }
        {
            int r = b_r;
            *(float4*)&Bs[r][b_c] = *(const float4*)&B[(size_t)(k0 + r) * BN + b_c];
        }
        __syncthreads();

        #pragma unroll
        for (int k = 0; k < BK; k++) {
            unsigned long long ra2[TM], rb2[TN / 2];
            #pragma unroll
            for (int i = 0; i < TM; i++) {
                float a = As[k][ty * TM + i];
                ra2[i] = pack2(a, a);
            }
            #pragma unroll
            for (int j = 0; j < TN / 2; j++)
                rb2[j] = *(const unsigned long long*)&Bs[k][tx * TN + 2 * j];
            #pragma unroll
            for (int i = 0; i < TM; i++)
                #pragma unroll
                for (int j = 0; j < TN / 2; j++)
                    fma2(acc2[i][j], ra2[i], rb2[j]);
        }
        __syncthreads();
    }

    #pragma unroll
    for (int i = 0; i < TM; i++) {
        int grow = block_row + ty * TM + i;
        if (grow < M) {
            float4 v = make_float4(lo32(acc2[i][0]), hi32(acc2[i][0]),
                                   lo32(acc2[i][1]), hi32(acc2[i][1]));
            *(float4*)&g_h2[(size_t)grow * BN + tx * TN] = v;
        }
    }
}

// ---------------------------------------------------------------------------
// Segment aggregation: warp per node; per-edge dis[s] (broadcast load),
// dis[dst] in epilogue.
__global__ void __launch_bounds__(256) agg128_relu(
    const float* __restrict__ bias)
{
    int gw = (blockIdx.x * blockDim.x + threadIdx.x) >> 5;
    int lane = threadIdx.x & 31;
    if (gw >= NN) return;
    int beg = g_off[gw], end = g_off[gw + 1];
    int c4 = lane * 4;

    float4 acc = make_float4(0.f, 0.f, 0.f, 0.f);
    int idx = beg;
    for (; idx + 4 <= end; idx += 4) {
        int s0 = g_src[idx + 0];
        int s1 = g_src[idx + 1];
        int s2 = g_src[idx + 2];
        int s3 = g_src[idx + 3];
        float n0 = g_dis[s0], n1 = g_dis[s1], n2 = g_dis[s2], n3 = g_dis[s3];
        float4 v0 = *(const float4*)(g_h1 + (size_t)s0 * 128 + c4);
        float4 v1 = *(const float4*)(g_h1 + (size_t)s1 * 128 + c4);
        float4 v2 = *(const float4*)(g_h1 + (size_t)s2 * 128 + c4);
        float4 v3 = *(const float4*)(g_h1 + (size_t)s3 * 128 + c4);
        acc.x = fmaf(n0, v0.x, acc.x); acc.y = fmaf(n0, v0.y, acc.y);
        acc.z = fmaf(n0, v0.z, acc.z); acc.w = fmaf(n0, v0.w, acc.w);
        acc.x = fmaf(n1, v1.x, acc.x); acc.y = fmaf(n1, v1.y, acc.y);
        acc.z = fmaf(n1, v1.z, acc.z); acc.w = fmaf(n1, v1.w, acc.w);
        acc.x = fmaf(n2, v2.x, acc.x); acc.y = fmaf(n2, v2.y, acc.y);
        acc.z = fmaf(n2, v2.z, acc.z); acc.w = fmaf(n2, v2.w, acc.w);
        acc.x = fmaf(n3, v3.x, acc.x); acc.y = fmaf(n3, v3.y, acc.y);
        acc.z = fmaf(n3, v3.z, acc.z); acc.w = fmaf(n3, v3.w, acc.w);
    }
    for (; idx < end; idx++) {
        int s = g_src[idx];
        float n = g_dis[s];
        float4 v = *(const float4*)(g_h1 + (size_t)s * 128 + c4);
        acc.x = fmaf(n, v.x, acc.x); acc.y = fmaf(n, v.y, acc.y);
        acc.z = fmaf(n, v.z, acc.z); acc.w = fmaf(n, v.w, acc.w);
    }
    float dd = g_dis[gw];
    float4 bb = *(const float4*)(bias + c4);
    acc.x = fmaxf(fmaf(dd, acc.x, bb.x), 0.f);
    acc.y = fmaxf(fmaf(dd, acc.y, bb.y), 0.f);
    acc.z = fmaxf(fmaf(dd, acc.z, bb.z), 0.f);
    acc.w = fmaxf(fmaf(dd, acc.w, bb.w), 0.f);
    *(float4*)(g_a1 + (size_t)gw * 128 + c4) = acc;
}

// last kernel: also zeroes g_deg/g_cnt for the next launch (warp per node)
__global__ void __launch_bounds__(256) agg64_out(
    const float* __restrict__ bias, float* __restrict__ OUT)
{
    int gw = (blockIdx.x * blockDim.x + threadIdx.x) >> 5;
    int lane = threadIdx.x & 31;
    if (gw >= NN) return;
    int beg = g_off[gw], end = g_off[gw + 1];
    int c2 = lane * 2;

    float2 acc = make_float2(0.f, 0.f);
    int idx = beg;
    for (; idx + 4 <= end; idx += 4) {
        int s0 = g_src[idx + 0];
        int s1 = g_src[idx + 1];
        int s2 = g_src[idx + 2];
        int s3 = g_src[idx + 3];
        float n0 = g_dis[s0], n1 = g_dis[s1], n2 = g_dis[s2], n3 = g_dis[s3];
        float2 v0 = *(const float2*)(g_h2 + (size_t)s0 * 64 + c2);
        float2 v1 = *(const float2*)(g_h2 + (size_t)s1 * 64 + c2);
        float2 v2 = *(const float2*)(g_h2 + (size_t)s2 * 64 + c2);
        float2 v3 = *(const float2*)(g_h2 + (size_t)s3 * 64 + c2);
        acc.x = fmaf(n0, v0.x, acc.x); acc.y = fmaf(n0, v0.y, acc.y);
        acc.x = fmaf(n1, v1.x, acc.x); acc.y = fmaf(n1, v1.y, acc.y);
        acc.x = fmaf(n2, v2.x, acc.x); acc.y = fmaf(n2, v2.y, acc.y);
        acc.x = fmaf(n3, v3.x, acc.x); acc.y = fmaf(n3, v3.y, acc.y);
    }
    for (; idx < end; idx++) {
        int s = g_src[idx];
        float n = g_dis[s];
        float2 v = *(const float2*)(g_h2 + (size_t)s * 64 + c2);
        acc.x = fmaf(n, v.x, acc.x); acc.y = fmaf(n, v.y, acc.y);
    }
    float dd = g_dis[gw];
    float2 bb = *(const float2*)(bias + c2);
    acc.x = fmaf(dd, acc.x, bb.x);
    acc.y = fmaf(dd, acc.y, bb.y);
    *(float2*)(OUT + (size_t)gw * 64 + c2) = acc;

    if (lane == 0) { g_deg[gw] = 0; g_cnt[gw] = 0; }   // reset for next launch
}

// ---------------------------------------------------------------------------
extern "C" void kernel_launch(void* const* d_in, const int* in_sizes, int n_in,
                              void* d_out, int out_size) {
    const float* x  = (const float*)d_in[0];
    const void*  ei = d_in[1];
    const float* W1 = (const float*)d_in[2];
    const float* b1 = (const float*)d_in[3];
    const float* W2 = (const float*)d_in[4];
    const float* b2 = (const float*)d_in[5];
    float*       out = (float*)d_out;

    // lazy one-time stream/event setup (host-side only, no device memory)
    static cudaStream_t s2 = nullptr;
    static cudaEvent_t evFork = nullptr, evJoin = nullptr;
    if (s2 == nullptr) {
        cudaStreamCreateWithFlags(&s2, cudaStreamNonBlocking);
        cudaEventCreateWithFlags(&evFork, cudaEventDisableTiming);
        cudaEventCreateWithFlags(&evJoin, cudaEventDisableTiming);
    }

    const int TB = 256;

    // fork: sgemm1 (x@W1, independent of graph prep) on s2
    cudaEventRecord(evFork, 0);
    cudaStreamWaitEvent(s2, evFork, 0);
    sgemm1<<<(NN + 127) / 128, 256, 0, s2>>>(x, W1, NN);
    cudaEventRecord(evJoin, s2);

    // graph prep on main stream (g_deg/g_cnt pre-zeroed by previous launch)
    detect_kernel<<<1, 256>>>((const int*)ei);
    degree_kernel<<<(NE + TB - 1) / TB, TB>>>(ei);
    scan_dis_kernel<<<1, 1024>>>();
    scatter_kernel<<<(ET + TB - 1) / TB, TB>>>(ei);

    // join, then rest of the pipeline
    cudaStreamWaitEvent(0, evJoin, 0);
    agg128_relu<<<(NN * 32 + TB - 1) / TB, TB>>>(b1);
    sgemm2<<<(NN + 127) / 128, 256>>>(W2, NN);
    agg64_out<<<(NN * 32 + TB - 1) / TB, TB>>>(b2, out);
}

// round 9
// speedup vs baseline: 1.5156x; 1.1895x over previous
#include <cuda_runtime.h>
#include <cuda_bf16.h>

// 2-layer GCN. Ahat = D^-1/2 (A+I) D^-1/2, factored as:
//   agg(h)[d] = dis[d] * sum_{s in N(d)} dis[s] * h[s]
// Pure GEMMs (stream-overlapped with graph prep), segment-sum aggregation
// over dst-sorted edges (4B src per edge). Multi-block 3-phase scan.

#define NN 50000
#define NE 800000
#define ET (NN + NE)
#define FIN 128
#define D1  128
#define NCLS 64
#define NBLK ((NN + 255) / 256)   // 196 scan blocks

// ---- device scratch (static, no allocation) ----
__device__ float g_h1[NN * D1];
__device__ float g_a1[NN * D1];
__device__ float g_h2[NN * NCLS];
__device__ int   g_deg[NN];      // zeroed by tail of previous launch
__device__ float g_dis[NN];
__device__ int   g_off[NN + 1];
__device__ int   g_cnt[NN];      // zeroed by tail of previous launch
__device__ int   g_src[ET];
__device__ int   g_bsum[NBLK];
__device__ int   g_boff[NBLK];
__device__ int   g_is64;

// ---- packed f32x2 helpers ----
__device__ __forceinline__ unsigned long long pack2(float lo, float hi) {
    unsigned long long r;
    asm("mov.b64 %0, {%1, %2};" : "=l"(r) : "f"(lo), "f"(hi));
    return r;
}
__device__ __forceinline__ void fma2(unsigned long long& d,
                                     unsigned long long a,
                                     unsigned long long b) {
    asm("fma.rn.f32x2 %0, %1, %2, %3;" : "=l"(d) : "l"(a), "l"(b), "l"(d));
}
__device__ __forceinline__ float lo32(unsigned long long v) {
    return __uint_as_float((unsigned)v);
}
__device__ __forceinline__ float hi32(unsigned long long v) {
    return __uint_as_float((unsigned)(v >> 32));
}

// ---------------------------------------------------------------------------
__global__ void detect_kernel(const int* __restrict__ raw) {
    __shared__ int nz;
    if (threadIdx.x == 0) nz = 0;
    __syncthreads();
    for (int k = threadIdx.x; k < 512; k += blockDim.x)
        if (raw[2 * k + 1] != 0) atomicOr(&nz, 1);
    __syncthreads();
    if (threadIdx.x == 0) g_is64 = (nz == 0) ? 1 : 0;
}

__device__ __forceinline__ int edge_at(const void* raw, int idx) {
    if (g_is64) return (int)((const long long*)raw)[idx];
    return ((const int*)raw)[idx];
}

__global__ void degree_kernel(const void* __restrict__ ei) {
    int e = blockIdx.x * blockDim.x + threadIdx.x;
    if (e < NE) atomicAdd(&g_deg[edge_at(ei, NE + e)], 1);
}

// ---- 3-phase scan: deg+1 -> exclusive offsets + dis ----
__global__ void __launch_bounds__(256) scan_p1() {
    __shared__ int wsum[8];
    int tid = threadIdx.x, lane = tid & 31, w = tid >> 5;
    int i = blockIdx.x * 256 + tid;
    int v = (i < NN) ? g_deg[i] + 1 : 0;
    int x = v;
    #pragma unroll
    for (int d = 16; d > 0; d >>= 1) x += __shfl_down_sync(0xffffffffu, x, d);
    if (lane == 0) wsum[w] = x;
    __syncthreads();
    if (tid < 8) {
        int y = wsum[tid];
        #pragma unroll
        for (int d = 4; d > 0; d >>= 1) y += __shfl_down_sync(0xffu, y, d);
        if (tid == 0) g_bsum[blockIdx.x] = y;
    }
}

__global__ void __launch_bounds__(256) scan_p2() {
    __shared__ int wsum[8];
    int tid = threadIdx.x, lane = tid & 31, w = tid >> 5;
    int v = (tid < NBLK) ? g_bsum[tid] : 0;
    int x = v;
    #pragma unroll
    for (int d = 1; d < 32; d <<= 1) {
        int t = __shfl_up_sync(0xffffffffu, x, d);
        if (lane >= d) x += t;
    }
    if (lane == 31) wsum[w] = x;
    __syncthreads();
    if (w == 0 && lane < 8) {
        int y = wsum[lane];
        #pragma unroll
        for (int d = 1; d < 8; d <<= 1) {
            int t = __shfl_up_sync(0xffu, y, d);
            if (lane >= d) y += t;
        }
        wsum[lane] = y;
    }
    __syncthreads();
    int excl = x - v + (w > 0 ? wsum[w - 1] : 0);
    if (tid < NBLK) g_boff[tid] = excl;
    if (tid == NBLK - 1) g_off[NN] = excl + v;   // == ET
}

__global__ void __launch_bounds__(256) scan_p3() {
    __shared__ int wsum[8];
    int tid = threadIdx.x, lane = tid & 31, w = tid >> 5;
    int i = blockIdx.x * 256 + tid;
    int v = 0;
    if (i < NN) {
        v = g_deg[i] + 1;
        g_dis[i] = rsqrtf((float)v);
    }
    int x = v;
    #pragma unroll
    for (int d = 1; d < 32; d <<= 1) {
        int t = __shfl_up_sync(0xffffffffu, x, d);
        if (lane >= d) x += t;
    }
    if (lane == 31) wsum[w] = x;
    __syncthreads();
    if (w == 0 && lane < 8) {
        int y = wsum[lane];
        #pragma unroll
        for (int d = 1; d < 8; d <<= 1) {
            int t = __shfl_up_sync(0xffu, y, d);
            if (lane >= d) y += t;
        }
        wsum[lane] = y;
    }
    __syncthreads();
    int excl = x - v + (w > 0 ? wsum[w - 1] : 0) + g_boff[blockIdx.x];
    if (i < NN) g_off[i] = excl;
}

__global__ void scatter_kernel(const void* __restrict__ ei) {
    int e = blockIdx.x * blockDim.x + threadIdx.x;
    if (e >= ET) return;
    int s, d;
    if (e < NE) { s = edge_at(ei, e); d = edge_at(ei, NE + e); }
    else        { s = d = e - NE; }
    int pos = g_off[d] + atomicAdd(&g_cnt[d], 1);
    g_src[pos] = s;
}

// ---------------------------------------------------------------------------
// Pure fp32 SGEMM (f32x2 mainloop), K=128, BM=128, BK=16, 256 threads.
__global__ void __launch_bounds__(256) sgemm1(
    const float* __restrict__ A, const float* __restrict__ B, int M)
{
    constexpr int BM = 128, BN = 128, BK = 16, K = 128, TM = 8, TN = 8;
    __shared__ float As[BK][BM];
    __shared__ float Bs[BK][BN];

    const int tid = threadIdx.x;
    const int block_row = blockIdx.x * BM;
    const int tx = tid % (BN / TN);
    const int ty = tid / (BN / TN);

    unsigned long long acc2[TM][TN / 2];
    #pragma unroll
    for (int i = 0; i < TM; i++)
        #pragma unroll
        for (int j = 0; j < TN / 2; j++) acc2[i][j] = 0ull;

    const int a_r = tid / 4;
    const int a_c = (tid % 4) * 4;
    const int b_r = tid / (BN / 4);
    const int b_c = (tid % (BN / 4)) * 4;

    for (int k0 = 0; k0 < K; k0 += BK) {
        #pragma unroll
        for (int it = 0; it < 2; it++) {
            int r = a_r + it * 64;
            int grow = block_row + r;
            float4 v = make_float4(0.f, 0.f, 0.f, 0.f);
            if (grow < M) v = *(const float4*)&A[(size_t)grow * K + k0 + a_c];
            As[a_c + 0][r] = v.x;
            As[a_c + 1][r] = v.y;
            As[a_c + 2][r] = v.z;
            As[a_c + 3][r] = v.w;
        }
        #pragma unroll
        for (int it = 0; it < 2; it++) {
            int r = b_r + it * 8;
            *(float4*)&Bs[r][b_c] = *(const float4*)&B[(size_t)(k0 + r) * BN + b_c];
        }
        __syncthreads();

        #pragma unroll
        for (int k = 0; k < BK; k++) {
            unsigned long long ra2[TM], rb2[TN / 2];
            #pragma unroll
            for (int i = 0; i < TM; i++) {
                float a = As[k][ty * TM + i];
                ra2[i] = pack2(a, a);
            }
            #pragma unroll
            for (int j = 0; j < TN / 2; j++)
                rb2[j] = *(const unsigned long long*)&Bs[k][tx * TN + 2 * j];
            #pragma unroll
            for (int i = 0; i < TM; i++)
                #pragma unroll
                for (int j = 0; j < TN / 2; j++)
                    fma2(acc2[i][j], ra2[i], rb2[j]);
        }
        __syncthreads();
    }

    #pragma unroll
    for (int i = 0; i < TM; i++) {
        int grow = block_row + ty * TM + i;
        if (grow < M) {
            #pragma unroll
            for (int j = 0; j < TN / 2; j += 2) {
                float4 v = make_float4(lo32(acc2[i][j]), hi32(acc2[i][j]),
                                       lo32(acc2[i][j + 1]), hi32(acc2[i][j + 1]));
                *(float4*)&g_h1[(size_t)grow * BN + tx * TN + 2 * j] = v;
            }
        }
    }
}

__global__ void __launch_bounds__(256) sgemm2(
    const float* __restrict__ B, int M)
{
    constexpr int BM = 128, BN = 64, BK = 16, K = 128, TM = 8, TN = 4;
    __shared__ float As[BK][BM];
    __shared__ float Bs[BK][BN];

    const int tid = threadIdx.x;
    const int block_row = blockIdx.x * BM;
    const int tx = tid % (BN / TN);
    const int ty = tid / (BN / TN);

    unsigned long long acc2[TM][TN / 2];
    #pragma unroll
    for (int i = 0; i < TM; i++)
        #pragma unroll
        for (int j = 0; j < TN / 2; j++) acc2[i][j] = 0ull;

    const int a_r = tid / 4;
    const int a_c = (tid % 4) * 4;
    const int b_r = tid / (BN / 4);
    const int b_c = (tid % (BN / 4)) * 4;

    for (int k0 = 0; k0 < K; k0 += BK) {
        #pragma unroll
        for (int it = 0; it < 2; it++) {
            int r = a_r + it * 64;
            int grow = block_row + r;
            float4 v = make_float4(0.f, 0.f, 0.f, 0.f);
            if (grow < M) v = *(const float4*)&g_a1[(size_t)grow * K + k0 + a_c];
            As[a_c + 0][r] = v.x;
            As[a_c + 1][r] = v.y;
            As[a_c + 2][r] = v.z;
            As[a_c + 3][r] = v.w;
        }
        {
            int r = b_r;
            *(float4*)&Bs[r][b_c] = *(const float4*)&B[(size_t)(k0 + r) * BN + b_c];
        }
        __syncthreads();

        #pragma unroll
        for (int k = 0; k < BK; k++) {
            unsigned long long ra2[TM], rb2[TN / 2];
            #pragma unroll
            for (int i = 0; i < TM; i++) {
                float a = As[k][ty * TM + i];
                ra2[i] = pack2(a, a);
            }
            #pragma unroll
            for (int j = 0; j < TN / 2; j++)
                rb2[j] = *(const unsigned long long*)&Bs[k][tx * TN + 2 * j];
            #pragma unroll
            for (int i = 0; i < TM; i++)
                #pragma unroll
                for (int j = 0; j < TN / 2; j++)
                    fma2(acc2[i][j], ra2[i], rb2[j]);
        }
        __syncthreads();
    }

    #pragma unroll
    for (int i = 0; i < TM; i++) {
        int grow = block_row + ty * TM + i;
        if (grow < M) {
            float4 v = make_float4(lo32(acc2[i][0]), hi32(acc2[i][0]),
                                   lo32(acc2[i][1]), hi32(acc2[i][1]));
            *(float4*)&g_h2[(size_t)grow * BN + tx * TN] = v;
        }
    }
}

// ---------------------------------------------------------------------------
// Segment aggregation: warp per node; per-edge dis[s], dis[dst] in epilogue.
__global__ void __launch_bounds__(256) agg128_relu(
    const float* __restrict__ bias)
{
    int gw = (blockIdx.x * blockDim.x + threadIdx.x) >> 5;
    int lane = threadIdx.x & 31;
    if (gw >= NN) return;
    int beg = g_off[gw], end = g_off[gw + 1];
    int c4 = lane * 4;

    float4 acc = make_float4(0.f, 0.f, 0.f, 0.f);
    int idx = beg;
    for (; idx + 4 <= end; idx += 4) {
        int s0 = g_src[idx + 0];
        int s1 = g_src[idx + 1];
        int s2 = g_src[idx + 2];
        int s3 = g_src[idx + 3];
        float n0 = g_dis[s0], n1 = g_dis[s1], n2 = g_dis[s2], n3 = g_dis[s3];
        float4 v0 = *(const float4*)(g_h1 + (size_t)s0 * 128 + c4);
        float4 v1 = *(const float4*)(g_h1 + (size_t)s1 * 128 + c4);
        float4 v2 = *(const float4*)(g_h1 + (size_t)s2 * 128 + c4);
        float4 v3 = *(const float4*)(g_h1 + (size_t)s3 * 128 + c4);
        acc.x = fmaf(n0, v0.x, acc.x); acc.y = fmaf(n0, v0.y, acc.y);
        acc.z = fmaf(n0, v0.z, acc.z); acc.w = fmaf(n0, v0.w, acc.w);
        acc.x = fmaf(n1, v1.x, acc.x); acc.y = fmaf(n1, v1.y, acc.y);
        acc.z = fmaf(n1, v1.z, acc.z); acc.w = fmaf(n1, v1.w, acc.w);
        acc.x = fmaf(n2, v2.x, acc.x); acc.y = fmaf(n2, v2.y, acc.y);
        acc.z = fmaf(n2, v2.z, acc.z); acc.w = fmaf(n2, v2.w, acc.w);
        acc.x = fmaf(n3, v3.x, acc.x); acc.y = fmaf(n3, v3.y, acc.y);
        acc.z = fmaf(n3, v3.z, acc.z); acc.w = fmaf(n3, v3.w, acc.w);
    }
    for (; idx < end; idx++) {
        int s = g_src[idx];
        float n = g_dis[s];
        float4 v = *(const float4*)(g_h1 + (size_t)s * 128 + c4);
        acc.x = fmaf(n, v.x, acc.x); acc.y = fmaf(n, v.y, acc.y);
        acc.z = fmaf(n, v.z, acc.z); acc.w = fmaf(n, v.w, acc.w);
    }
    float dd = g_dis[gw];
    float4 bb = *(const float4*)(bias + c4);
    acc.x = fmaxf(fmaf(dd, acc.x, bb.x), 0.f);
    acc.y = fmaxf(fmaf(dd, acc.y, bb.y), 0.f);
    acc.z = fmaxf(fmaf(dd, acc.z, bb.z), 0.f);
    acc.w = fmaxf(fmaf(dd, acc.w, bb.w), 0.f);
    *(float4*)(g_a1 + (size_t)gw * 128 + c4) = acc;
}

// last kernel: also zeroes g_deg/g_cnt for the next launch
__global__ void __launch_bounds__(256) agg64_out(
    const float* __restrict__ bias, float* __restrict__ OUT)
{
    int gw = (blockIdx.x * blockDim.x + threadIdx.x) >> 5;
    int lane = threadIdx.x & 31;
    if (gw >= NN) return;
    int beg = g_off[gw], end = g_off[gw + 1];
    int c2 = lane * 2;

    float2 acc = make_float2(0.f, 0.f);
    int idx = beg;
    for (; idx + 4 <= end; idx += 4) {
        int s0 = g_src[idx + 0];
        int s1 = g_src[idx + 1];
        int s2 = g_src[idx + 2];
        int s3 = g_src[idx + 3];
        float n0 = g_dis[s0], n1 = g_dis[s1], n2 = g_dis[s2], n3 = g_dis[s3];
        float2 v0 = *(const float2*)(g_h2 + (size_t)s0 * 64 + c2);
        float2 v1 = *(const float2*)(g_h2 + (size_t)s1 * 64 + c2);
        float2 v2 = *(const float2*)(g_h2 + (size_t)s2 * 64 + c2);
        float2 v3 = *(const float2*)(g_h2 + (size_t)s3 * 64 + c2);
        acc.x = fmaf(n0, v0.x, acc.x); acc.y = fmaf(n0, v0.y, acc.y);
        acc.x = fmaf(n1, v1.x, acc.x); acc.y = fmaf(n1, v1.y, acc.y);
        acc.x = fmaf(n2, v2.x, acc.x); acc.y = fmaf(n2, v2.y, acc.y);
        acc.x = fmaf(n3, v3.x, acc.x); acc.y = fmaf(n3, v3.y, acc.y);
    }
    for (; idx < end; idx++) {
        int s = g_src[idx];
        float n = g_dis[s];
        float2 v = *(const float2*)(g_h2 + (size_t)s * 64 + c2);
        acc.x = fmaf(n, v.x, acc.x); acc.y = fmaf(n, v.y, acc.y);
    }
    float dd = g_dis[gw];
    float2 bb = *(const float2*)(bias + c2);
    acc.x = fmaf(dd, acc.x, bb.x);
    acc.y = fmaf(dd, acc.y, bb.y);
    *(float2*)(OUT + (size_t)gw * 64 + c2) = acc;

    if (lane == 0) { g_deg[gw] = 0; g_cnt[gw] = 0; }   // reset for next launch
}

// ---------------------------------------------------------------------------
extern "C" void kernel_launch(void* const* d_in, const int* in_sizes, int n_in,
                              void* d_out, int out_size) {
    const float* x  = (const float*)d_in[0];
    const void*  ei = d_in[1];
    const float* W1 = (const float*)d_in[2];
    const float* b1 = (const float*)d_in[3];
    const float* W2 = (const float*)d_in[4];
    const float* b2 = (const float*)d_in[5];
    float*       out = (float*)d_out;

    static cudaStream_t s2 = nullptr;
    static cudaEvent_t evFork = nullptr, evJoin = nullptr;
    if (s2 == nullptr) {
        cudaStreamCreateWithFlags(&s2, cudaStreamNonBlocking);
        cudaEventCreateWithFlags(&evFork, cudaEventDisableTiming);
        cudaEventCreateWithFlags(&evJoin, cudaEventDisableTiming);
    }

    const int TB = 256;

    // fork: sgemm1 (x@W1, independent of graph prep) on s2
    cudaEventRecord(evFork, 0);
    cudaStreamWaitEvent(s2, evFork, 0);
    sgemm1<<<(NN + 127) / 128, 256, 0, s2>>>(x, W1, NN);
    cudaEventRecord(evJoin, s2);

    // graph prep on main stream
    detect_kernel<<<1, 256>>>((const int*)ei);
    degree_kernel<<<(NE + TB - 1) / TB, TB>>>(ei);
    scan_p1<<<NBLK, 256>>>();
    scan_p2<<<1, 256>>>();
    scan_p3<<<NBLK, 256>>>();
    scatter_kernel<<<(ET + TB - 1) / TB, TB>>>(ei);

    // join, then rest of the pipeline
    cudaStreamWaitEvent(0, evJoin, 0);
    agg128_relu<<<(NN * 32 + TB - 1) / TB, TB>>>(b1);
    sgemm2<<<(NN + 127) / 128, 256>>>(W2, NN);
    agg64_out<<<(NN * 32 + TB - 1) / TB, TB>>>(b2, out);
}

// round 10
// speedup vs baseline: 1.5219x; 1.0042x over previous
#include <cuda_runtime.h>
#include <cuda_bf16.h>

// 2-layer GCN. Ahat = D^-1/2 (A+I) D^-1/2, factored as:
//   agg(h)[d] = dis[d] * sum_{s in N(d)} dis[s] * h[s]
// int32 edge_index (JAX x64-demoted). Pure GEMMs with register-prefetch
// pipelines (f32x2 FFMA), stream-overlapped with graph prep; counting-sort
// by dst; warp-per-node segment aggregation.

#define NN 50000
#define NE 800000
#define ET (NN + NE)
#define FIN 128
#define D1  128
#define NCLS 64
#define NBLK ((NN + 255) / 256)   // 196 scan blocks

// ---- device scratch (static, no allocation) ----
__device__ float g_h1[NN * D1];
__device__ float g_a1[NN * D1];
__device__ float g_h2[NN * NCLS];
__device__ int   g_deg[NN];      // zeroed by tail of previous launch
__device__ float g_dis[NN];
__device__ int   g_off[NN + 1];
__device__ int   g_cnt[NN];      // zeroed by tail of previous launch
__device__ int   g_src[ET];
__device__ int   g_bsum[NBLK];
__device__ int   g_boff[NBLK];
__device__ int   g_tick;         // reset by last scan block

// ---- packed f32x2 helpers ----
__device__ __forceinline__ unsigned long long pack2(float lo, float hi) {
    unsigned long long r;
    asm("mov.b64 %0, {%1, %2};" : "=l"(r) : "f"(lo), "f"(hi));
    return r;
}
__device__ __forceinline__ void fma2(unsigned long long& d,
                                     unsigned long long a,
                                     unsigned long long b) {
    asm("fma.rn.f32x2 %0, %1, %2, %3;" : "=l"(d) : "l"(a), "l"(b), "l"(d));
}
__device__ __forceinline__ float lo32(unsigned long long v) {
    return __uint_as_float((unsigned)v);
}
__device__ __forceinline__ float hi32(unsigned long long v) {
    return __uint_as_float((unsigned)(v >> 32));
}

// ---------------------------------------------------------------------------
__global__ void degree_kernel(const int* __restrict__ ei) {
    int e = blockIdx.x * blockDim.x + threadIdx.x;   // handles 2 edges
    if (e < NE / 2) {
        int2 d2 = ((const int2*)(ei + NE))[e];
        atomicAdd(&g_deg[d2.x], 1);
        atomicAdd(&g_deg[d2.y], 1);
    }
}

// fused phase1+2: per-block reduce of deg+1; last block scans block sums.
__global__ void __launch_bounds__(256) scan_p1p2() {
    __shared__ int wsum[8];
    __shared__ int amLast;
    int tid = threadIdx.x, lane = tid & 31, w = tid >> 5;
    int i = blockIdx.x * 256 + tid;
    int v = (i < NN) ? g_deg[i] + 1 : 0;
    int x = v;
    #pragma unroll
    for (int d = 16; d > 0; d >>= 1) x += __shfl_down_sync(0xffffffffu, x, d);
    if (lane == 0) wsum[w] = x;
    __syncthreads();
    if (tid < 8) {
        int y = wsum[tid];
        #pragma unroll
        for (int d = 4; d > 0; d >>= 1) y += __shfl_down_sync(0xffu, y, d);
        if (tid == 0) g_bsum[blockIdx.x] = y;
    }
    if (tid == 0) {
        __threadfence();
        amLast = (atomicAdd(&g_tick, 1) == NBLK - 1) ? 1 : 0;
    }
    __syncthreads();
    if (amLast) {
        // scan the NBLK block sums (NBLK <= 256)
        int bv = (tid < NBLK) ? g_bsum[tid] : 0;
        int bx = bv;
        #pragma unroll
        for (int d = 1; d < 32; d <<= 1) {
            int t = __shfl_up_sync(0xffffffffu, bx, d);
            if (lane >= d) bx += t;
        }
        if (lane == 31) wsum[w] = bx;
        __syncthreads();
        if (w == 0 && lane < 8) {
            int y = wsum[lane];
            #pragma unroll
            for (int d = 1; d < 8; d <<= 1) {
                int t = __shfl_up_sync(0xffu, y, d);
                if (lane >= d) y += t;
            }
            wsum[lane] = y;
        }
        __syncthreads();
        int excl = bx - bv + (w > 0 ? wsum[w - 1] : 0);
        if (tid < NBLK) g_boff[tid] = excl;
        if (tid == NBLK - 1) g_off[NN] = excl + bv;   // == ET
        if (tid == 0) g_tick = 0;                     // reset for next launch
    }
}

__global__ void __launch_bounds__(256) scan_p3() {
    __shared__ int wsum[8];
    int tid = threadIdx.x, lane = tid & 31, w = tid >> 5;
    int i = blockIdx.x * 256 + tid;
    int v = 0;
    if (i < NN) {
        v = g_deg[i] + 1;
        g_dis[i] = rsqrtf((float)v);
    }
    int x = v;
    #pragma unroll
    for (int d = 1; d < 32; d <<= 1) {
        int t = __shfl_up_sync(0xffffffffu, x, d);
        if (lane >= d) x += t;
    }
    if (lane == 31) wsum[w] = x;
    __syncthreads();
    if (w == 0 && lane < 8) {
        int y = wsum[lane];
        #pragma unroll
        for (int d = 1; d < 8; d <<= 1) {
            int t = __shfl_up_sync(0xffu, y, d);
            if (lane >= d) y += t;
        }
        wsum[lane] = y;
    }
    __syncthreads();
    int excl = x - v + (w > 0 ? wsum[w - 1] : 0) + g_boff[blockIdx.x];
    if (i < NN) g_off[i] = excl;
}

__global__ void scatter_kernel(const int* __restrict__ ei) {
    int e = blockIdx.x * blockDim.x + threadIdx.x;
    if (e >= ET) return;
    int s, d;
    if (e < NE) { s = ei[e]; d = ei[NE + e]; }
    else        { s = d = e - NE; }
    int pos = g_off[d] + atomicAdd(&g_cnt[d], 1);
    g_src[pos] = s;
}

// ---------------------------------------------------------------------------
// fp32 SGEMM, register-prefetch pipeline, f32x2 mainloop.
// K=128, BM=128, BK=16, 256 threads.
__global__ void __launch_bounds__(256) sgemm1(
    const float* __restrict__ A, const float* __restrict__ B, int M)
{
    constexpr int BM = 128, BN = 128, BK = 16, K = 128, TM = 8, TN = 8;
    __shared__ float As[BK][BM];
    __shared__ float Bs[BK][BN];

    const int tid = threadIdx.x;
    const int block_row = blockIdx.x * BM;
    const int tx = tid % (BN / TN);
    const int ty = tid / (BN / TN);

    unsigned long long acc2[TM][TN / 2];
    #pragma unroll
    for (int i = 0; i < TM; i++)
        #pragma unroll
        for (int j = 0; j < TN / 2; j++) acc2[i][j] = 0ull;

    const int a_r = tid / 4;
    const int a_c = (tid % 4) * 4;
    const int b_r = tid / 32;           // 0..7
    const int b_c = (tid % 32) * 4;

    float4 pa[2], pb[2];
    // prefetch tile 0
    #pragma unroll
    for (int it = 0; it < 2; it++) {
        int grow = block_row + a_r + it * 64;
        pa[it] = (grow < M) ? *(const float4*)&A[(size_t)grow * K + a_c]
                            : make_float4(0.f, 0.f, 0.f, 0.f);
        pb[it] = *(const float4*)&B[(size_t)(b_r + it * 8) * BN + b_c];
    }

    for (int t = 0; t < K / BK; t++) {
        __syncthreads();        // buffer free from previous compute
        #pragma unroll
        for (int it = 0; it < 2; it++) {
            int r = a_r + it * 64;
            As[a_c + 0][r] = pa[it].x;
            As[a_c + 1][r] = pa[it].y;
            As[a_c + 2][r] = pa[it].z;
            As[a_c + 3][r] = pa[it].w;
            *(float4*)&Bs[b_r + it * 8][b_c] = pb[it];
        }
        if (t < K / BK - 1) {   // prefetch next tile (flies during compute)
            int k0 = (t + 1) * BK;
            #pragma unroll
            for (int it = 0; it < 2; it++) {
                int grow = block_row + a_r + it * 64;
                pa[it] = (grow < M) ? *(const float4*)&A[(size_t)grow * K + k0 + a_c]
                                    : make_float4(0.f, 0.f, 0.f, 0.f);
                pb[it] = *(const float4*)&B[(size_t)(k0 + b_r + it * 8) * BN + b_c];
            }
        }
        __syncthreads();

        #pragma unroll
        for (int k = 0; k < BK; k++) {
            unsigned long long ra2[TM], rb2[TN / 2];
            #pragma unroll
            for (int i = 0; i < TM; i++) {
                float a = As[k][ty * TM + i];
                ra2[i] = pack2(a, a);
            }
            #pragma unroll
            for (int j = 0; j < TN / 2; j++)
                rb2[j] = *(const unsigned long long*)&Bs[k][tx * TN + 2 * j];
            #pragma unroll
            for (int i = 0; i < TM; i++)
                #pragma unroll
                for (int j = 0; j < TN / 2; j++)
                    fma2(acc2[i][j], ra2[i], rb2[j]);
        }
    }

    #pragma unroll
    for (int i = 0; i < TM; i++) {
        int grow = block_row + ty * TM + i;
        if (grow < M) {
            #pragma unroll
            for (int j = 0; j < TN / 2; j += 2) {
                float4 v = make_float4(lo32(acc2[i][j]), hi32(acc2[i][j]),
                                       lo32(acc2[i][j + 1]), hi32(acc2[i][j + 1]));
                *(float4*)&g_h1[(size_t)grow * BN + tx * TN + 2 * j] = v;
            }
        }
    }
}

__global__ void __launch_bounds__(256) sgemm2(
    const float* __restrict__ B, int M)
{
    constexpr int BM = 128, BN = 64, BK = 16, K = 128, TM = 8, TN = 4;
    __shared__ float As[BK][BM];
    __shared__ float Bs[BK][BN];

    const int tid = threadIdx.x;
    const int block_row = blockIdx.x * BM;
    const int tx = tid % (BN / TN);
    const int ty = tid / (BN / TN);

    unsigned long long acc2[TM][TN / 2];
    #pragma unroll
    for (int i = 0; i < TM; i++)
        #pragma unroll
        for (int j = 0; j < TN / 2; j++) acc2[i][j] = 0ull;

    const int a_r = tid / 4;
    const int a_c = (tid % 4) * 4;
    const int b_r = tid / 16;           // 0..15
    const int b_c = (tid % 16) * 4;

    float4 pa[2], pb;
    #pragma unroll
    for (int it = 0; it < 2; it++) {
        int grow = block_row + a_r + it * 64;
        pa[it] = (grow < M) ? *(const float4*)&g_a1[(size_t)grow * K + a_c]
                            : make_float4(0.f, 0.f, 0.f, 0.f);
    }
    pb = *(const float4*)&B[(size_t)b_r * BN + b_c];

    for (int t = 0; t < K / BK; t++) {
        __syncthreads();
        #pragma unroll
        for (int it = 0; it < 2; it++) {
            int r = a_r + it * 64;
            As[a_c + 0][r] = pa[it].x;
            As[a_c + 1][r] = pa[it].y;
            As[a_c + 2][r] = pa[it].z;
            As[a_c + 3][r] = pa[it].w;
        }
        *(float4*)&Bs[b_r][b_c] = pb;
        if (t < K / BK - 1) {
            int k0 = (t + 1) * BK;
            #pragma unroll
            for (int it = 0; it < 2; it++) {
                int grow = block_row + a_r + it * 64;
                pa[it] = (grow < M) ? *(const float4*)&g_a1[(size_t)grow * K + k0 + a_c]
                                    : make_float4(0.f, 0.f, 0.f, 0.f);
            }
            pb = *(const float4*)&B[(size_t)(k0 + b_r) * BN + b_c];
        }
        __syncthreads();

        #pragma unroll
        for (int k = 0; k < BK; k++) {
            unsigned long long ra2[TM], rb2[TN / 2];
            #pragma unroll
            for (int i = 0; i < TM; i++) {
                float a = As[k][ty * TM + i];
                ra2[i] = pack2(a, a);
            }
            #pragma unroll
            for (int j = 0; j < TN / 2; j++)
                rb2[j] = *(const unsigned long long*)&Bs[k][tx * TN + 2 * j];
            #pragma unroll
            for (int i = 0; i < TM; i++)
                #pragma unroll
                for (int j = 0; j < TN / 2; j++)
                    fma2(acc2[i][j], ra2[i], rb2[j]);
        }
    }

    #pragma unroll
    for (int i = 0; i < TM; i++) {
        int grow = block_row + ty * TM + i;
        if (grow < M) {
            float4 v = make_float4(lo32(acc2[i][0]), hi32(acc2[i][0]),
                                   lo32(acc2[i][1]), hi32(acc2[i][1]));
            *(float4*)&g_h2[(size_t)grow * BN + tx * TN] = v;
        }
    }
}

// ---------------------------------------------------------------------------
// Segment aggregation: warp per node; per-edge dis[s], dis[dst] in epilogue.
__global__ void __launch_bounds__(256) agg128_relu(
    const float* __restrict__ bias)
{
    int gw = (blockIdx.x * blockDim.x + threadIdx.x) >> 5;
    int lane = threadIdx.x & 31;
    if (gw >= NN) return;
    int beg = g_off[gw], end = g_off[gw + 1];
    int c4 = lane * 4;

    float4 acc = make_float4(0.f, 0.f, 0.f, 0.f);
    int idx = beg;
    for (; idx + 4 <= end; idx += 4) {
        int s0 = g_src[idx + 0];
        int s1 = g_src[idx + 1];
        int s2 = g_src[idx + 2];
        int s3 = g_src[idx + 3];
        float n0 = g_dis[s0], n1 = g_dis[s1], n2 = g_dis[s2], n3 = g_dis[s3];
        float4 v0 = *(const float4*)(g_h1 + (size_t)s0 * 128 + c4);
        float4 v1 = *(const float4*)(g_h1 + (size_t)s1 * 128 + c4);
        float4 v2 = *(const float4*)(g_h1 + (size_t)s2 * 128 + c4);
        float4 v3 = *(const float4*)(g_h1 + (size_t)s3 * 128 + c4);
        acc.x = fmaf(n0, v0.x, acc.x); acc.y = fmaf(n0, v0.y, acc.y);
        acc.z = fmaf(n0, v0.z, acc.z); acc.w = fmaf(n0, v0.w, acc.w);
        acc.x = fmaf(n1, v1.x, acc.x); acc.y = fmaf(n1, v1.y, acc.y);
        acc.z = fmaf(n1, v1.z, acc.z); acc.w = fmaf(n1, v1.w, acc.w);
        acc.x = fmaf(n2, v2.x, acc.x); acc.y = fmaf(n2, v2.y, acc.y);
        acc.z = fmaf(n2, v2.z, acc.z); acc.w = fmaf(n2, v2.w, acc.w);
        acc.x = fmaf(n3, v3.x, acc.x); acc.y = fmaf(n3, v3.y, acc.y);
        acc.z = fmaf(n3, v3.z, acc.z); acc.w = fmaf(n3, v3.w, acc.w);
    }
    for (; idx < end; idx++) {
        int s = g_src[idx];
        float n = g_dis[s];
        float4 v = *(const float4*)(g_h1 + (size_t)s * 128 + c4);
        acc.x = fmaf(n, v.x, acc.x); acc.y = fmaf(n, v.y, acc.y);
        acc.z = fmaf(n, v.z, acc.z); acc.w = fmaf(n, v.w, acc.w);
    }
    float dd = g_dis[gw];
    float4 bb = *(const float4*)(bias + c4);
    acc.x = fmaxf(fmaf(dd, acc.x, bb.x), 0.f);
    acc.y = fmaxf(fmaf(dd, acc.y, bb.y), 0.f);
    acc.z = fmaxf(fmaf(dd, acc.z, bb.z), 0.f);
    acc.w = fmaxf(fmaf(dd, acc.w, bb.w), 0.f);
    *(float4*)(g_a1 + (size_t)gw * 128 + c4) = acc;
}

// last kernel: also zeroes g_deg/g_cnt for the next launch
__global__ void __launch_bounds__(256) agg64_out(
    const float* __restrict__ bias, float* __restrict__ OUT)
{
    int gw = (blockIdx.x * blockDim.x + threadIdx.x) >> 5;
    int lane = threadIdx.x & 31;
    if (gw >= NN) return;
    int beg = g_off[gw], end = g_off[gw + 1];
    int c2 = lane * 2;

    float2 acc = make_float2(0.f, 0.f);
    int idx = beg;
    for (; idx + 4 <= end; idx += 4) {
        int s0 = g_src[idx + 0];
        int s1 = g_src[idx + 1];
        int s2 = g_src[idx + 2];
        int s3 = g_src[idx + 3];
        float n0 = g_dis[s0], n1 = g_dis[s1], n2 = g_dis[s2], n3 = g_dis[s3];
        float2 v0 = *(const float2*)(g_h2 + (size_t)s0 * 64 + c2);
        float2 v1 = *(const float2*)(g_h2 + (size_t)s1 * 64 + c2);
        float2 v2 = *(const float2*)(g_h2 + (size_t)s2 * 64 + c2);
        float2 v3 = *(const float2*)(g_h2 + (size_t)s3 * 64 + c2);
        acc.x = fmaf(n0, v0.x, acc.x); acc.y = fmaf(n0, v0.y, acc.y);
        acc.x = fmaf(n1, v1.x, acc.x); acc.y = fmaf(n1, v1.y, acc.y);
        acc.x = fmaf(n2, v2.x, acc.x); acc.y = fmaf(n2, v2.y, acc.y);
        acc.x = fmaf(n3, v3.x, acc.x); acc.y = fmaf(n3, v3.y, acc.y);
    }
    for (; idx < end; idx++) {
        int s = g_src[idx];
        float n = g_dis[s];
        float2 v = *(const float2*)(g_h2 + (size_t)s * 64 + c2);
        acc.x = fmaf(n, v.x, acc.x); acc.y = fmaf(n, v.y, acc.y);
    }
    float dd = g_dis[gw];
    float2 bb = *(const float2*)(bias + c2);
    acc.x = fmaf(dd, acc.x, bb.x);
    acc.y = fmaf(dd, acc.y, bb.y);
    *(float2*)(OUT + (size_t)gw * 64 + c2) = acc;

    if (lane == 0) { g_deg[gw] = 0; g_cnt[gw] = 0; }   // reset for next launch
}

// ---------------------------------------------------------------------------
extern "C" void kernel_launch(void* const* d_in, const int* in_sizes, int n_in,
                              void* d_out, int out_size) {
    const float* x  = (const float*)d_in[0];
    const int*   ei = (const int*)d_in[1];
    const float* W1 = (const float*)d_in[2];
    const float* b1 = (const float*)d_in[3];
    const float* W2 = (const float*)d_in[4];
    const float* b2 = (const float*)d_in[5];
    float*       out = (float*)d_out;

    static cudaStream_t s2 = nullptr;
    static cudaEvent_t evFork = nullptr, evJoin = nullptr;
    if (s2 == nullptr) {
        cudaStreamCreateWithFlags(&s2, cudaStreamNonBlocking);
        cudaEventCreateWithFlags(&evFork, cudaEventDisableTiming);
        cudaEventCreateWithFlags(&evJoin, cudaEventDisableTiming);
    }

    const int TB = 256;

    // fork: sgemm1 (x@W1, independent of graph prep) on s2
    cudaEventRecord(evFork, 0);
    cudaStreamWaitEvent(s2, evFork, 0);
    sgemm1<<<(NN + 127) / 128, 256, 0, s2>>>(x, W1, NN);
    cudaEventRecord(evJoin, s2);

    // graph prep on main stream
    degree_kernel<<<(NE / 2 + TB - 1) / TB, TB>>>(ei);
    scan_p1p2<<<NBLK, 256>>>();
    scan_p3<<<NBLK, 256>>>();
    scatter_kernel<<<(ET + TB - 1) / TB, TB>>>(ei);

    // join, then rest of the pipeline
    cudaStreamWaitEvent(0, evJoin, 0);
    agg128_relu<<<(NN * 32 + TB - 1) / TB, TB>>>(b1);
    sgemm2<<<(NN + 127) / 128, 256>>>(W2, NN);
    agg64_out<<<(NN * 32 + TB - 1) / TB, TB>>>(b2, out);
}

// round 11
// speedup vs baseline: 1.7561x; 1.1539x over previous
#include <cuda_runtime.h>
#include <cuda_bf16.h>
#include <cuda_fp16.h>

// 2-layer GCN. Ahat = D^-1/2 (A+I) D^-1/2, factored as:
//   agg(h)[d] = dis[d] * sum_{s in N(d)} dis[s] * h[s]
// int32 edges; counting-sort by dst; warp-per-node segment aggregation.
// h1/h2 intermediates stored fp16 (halves gather traffic); fp32 accumulate.

#define NN 50000
#define NE 800000
#define ET (NN + NE)
#define FIN 128
#define D1  128
#define NCLS 64
#define NBLK ((NN + 255) / 256)

// ---- device scratch (static, no allocation) ----
__device__ __half g_h1[NN * D1];     // fp16 x@W1
__device__ float  g_a1[NN * D1];     // fp32 relu(agg)
__device__ __half g_h2[NN * NCLS];   // fp16 a1@W2
__device__ int    g_deg[NN];         // zeroed by tail of previous launch
__device__ float  g_dis[NN];
__device__ int    g_off[NN + 1];
__device__ int    g_cnt[NN];         // zeroed by tail of previous launch
__device__ int    g_src[ET];
__device__ int    g_bsum[NBLK];
__device__ int    g_boff[NBLK];
__device__ int    g_tick;            // reset by last scan block

// ---- packed f32x2 helpers ----
__device__ __forceinline__ unsigned long long pack2(float lo, float hi) {
    unsigned long long r;
    asm("mov.b64 %0, {%1, %2};" : "=l"(r) : "f"(lo), "f"(hi));
    return r;
}
__device__ __forceinline__ void fma2(unsigned long long& d,
                                     unsigned long long a,
                                     unsigned long long b) {
    asm("fma.rn.f32x2 %0, %1, %2, %3;" : "=l"(d) : "l"(a), "l"(b), "l"(d));
}
__device__ __forceinline__ float lo32(unsigned long long v) {
    return __uint_as_float((unsigned)v);
}
__device__ __forceinline__ float hi32(unsigned long long v) {
    return __uint_as_float((unsigned)(v >> 32));
}
__device__ __forceinline__ float4 h4_to_f4(uint2 u) {
    __half2 a = *reinterpret_cast<__half2*>(&u.x);
    __half2 b = *reinterpret_cast<__half2*>(&u.y);
    float2 fa = __half22float2(a), fb = __half22float2(b);
    return make_float4(fa.x, fa.y, fb.x, fb.y);
}
__device__ __forceinline__ float2 h2_to_f2(unsigned u) {
    __half2 a = *reinterpret_cast<__half2*>(&u);
    return __half22float2(a);
}

// ---------------------------------------------------------------------------
__global__ void degree_kernel(const int* __restrict__ ei) {
    int e = blockIdx.x * blockDim.x + threadIdx.x;
    if (e < NE / 2) {
        int2 d2 = ((const int2*)(ei + NE))[e];
        atomicAdd(&g_deg[d2.x], 1);
        atomicAdd(&g_deg[d2.y], 1);
    }
}

// fused phase1+2: per-block reduce of deg+1; last block scans block sums.
__global__ void __launch_bounds__(256) scan_p1p2() {
    __shared__ int wsum[8];
    __shared__ int amLast;
    int tid = threadIdx.x, lane = tid & 31, w = tid >> 5;
    int i = blockIdx.x * 256 + tid;
    int v = (i < NN) ? g_deg[i] + 1 : 0;
    int x = v;
    #pragma unroll
    for (int d = 16; d > 0; d >>= 1) x += __shfl_down_sync(0xffffffffu, x, d);
    if (lane == 0) wsum[w] = x;
    __syncthreads();
    if (tid < 8) {
        int y = wsum[tid];
        #pragma unroll
        for (int d = 4; d > 0; d >>= 1) y += __shfl_down_sync(0xffu, y, d);
        if (tid == 0) g_bsum[blockIdx.x] = y;
    }
    if (tid == 0) {
        __threadfence();
        amLast = (atomicAdd(&g_tick, 1) == NBLK - 1) ? 1 : 0;
    }
    __syncthreads();
    if (amLast) {
        int bv = (tid < NBLK) ? g_bsum[tid] : 0;
        int bx = bv;
        #pragma unroll
        for (int d = 1; d < 32; d <<= 1) {
            int t = __shfl_up_sync(0xffffffffu, bx, d);
            if (lane >= d) bx += t;
        }
        if (lane == 31) wsum[w] = bx;
        __syncthreads();
        if (w == 0 && lane < 8) {
            int y = wsum[lane];
            #pragma unroll
            for (int d = 1; d < 8; d <<= 1) {
                int t = __shfl_up_sync(0xffu, y, d);
                if (lane >= d) y += t;
            }
            wsum[lane] = y;
        }
        __syncthreads();
        int excl = bx - bv + (w > 0 ? wsum[w - 1] : 0);
        if (tid < NBLK) g_boff[tid] = excl;
        if (tid == NBLK - 1) g_off[NN] = excl + bv;   // == ET
        if (tid == 0) g_tick = 0;
    }
}

__global__ void __launch_bounds__(256) scan_p3() {
    __shared__ int wsum[8];
    int tid = threadIdx.x, lane = tid & 31, w = tid >> 5;
    int i = blockIdx.x * 256 + tid;
    int v = 0;
    if (i < NN) {
        v = g_deg[i] + 1;
        g_dis[i] = rsqrtf((float)v);
    }
    int x = v;
    #pragma unroll
    for (int d = 1; d < 32; d <<= 1) {
        int t = __shfl_up_sync(0xffffffffu, x, d);
        if (lane >= d) x += t;
    }
    if (lane == 31) wsum[w] = x;
    __syncthreads();
    if (w == 0 && lane < 8) {
        int y = wsum[lane];
        #pragma unroll
        for (int d = 1; d < 8; d <<= 1) {
            int t = __shfl_up_sync(0xffu, y, d);
            if (lane >= d) y += t;
        }
        wsum[lane] = y;
    }
    __syncthreads();
    int excl = x - v + (w > 0 ? wsum[w - 1] : 0) + g_boff[blockIdx.x];
    if (i < NN) g_off[i] = excl;
}

__global__ void scatter_kernel(const int* __restrict__ ei) {
    int e = blockIdx.x * blockDim.x + threadIdx.x;
    if (e >= ET) return;
    int s, d;
    if (e < NE) { s = ei[e]; d = ei[NE + e]; }
    else        { s = d = e - NE; }
    int pos = g_off[d] + atomicAdd(&g_cnt[d], 1);
    g_src[pos] = s;
}

// ---------------------------------------------------------------------------
// fp32 SGEMM, register-prefetch pipeline, f32x2 mainloop, fp16 output.
__global__ void __launch_bounds__(256) sgemm1(
    const float* __restrict__ A, const float* __restrict__ B, int M)
{
    constexpr int BM = 128, BN = 128, BK = 16, K = 128, TM = 8, TN = 8;
    __shared__ float As[BK][BM];
    __shared__ float Bs[BK][BN];

    const int tid = threadIdx.x;
    const int block_row = blockIdx.x * BM;
    const int tx = tid % (BN / TN);
    const int ty = tid / (BN / TN);

    unsigned long long acc2[TM][TN / 2];
    #pragma unroll
    for (int i = 0; i < TM; i++)
        #pragma unroll
        for (int j = 0; j < TN / 2; j++) acc2[i][j] = 0ull;

    const int a_r = tid / 4;
    const int a_c = (tid % 4) * 4;
    const int b_r = tid / 32;
    const int b_c = (tid % 32) * 4;

    float4 pa[2], pb[2];
    #pragma unroll
    for (int it = 0; it < 2; it++) {
        int grow = block_row + a_r + it * 64;
        pa[it] = (grow < M) ? *(const float4*)&A[(size_t)grow * K + a_c]
                            : make_float4(0.f, 0.f, 0.f, 0.f);
        pb[it] = *(const float4*)&B[(size_t)(b_r + it * 8) * BN + b_c];
    }

    for (int t = 0; t < K / BK; t++) {
        __syncthreads();
        #pragma unroll
        for (int it = 0; it < 2; it++) {
            int r = a_r + it * 64;
            As[a_c + 0][r] = pa[it].x;
            As[a_c + 1][r] = pa[it].y;
            As[a_c + 2][r] = pa[it].z;
            As[a_c + 3][r] = pa[it].w;
            *(float4*)&Bs[b_r + it * 8][b_c] = pb[it];
        }
        if (t < K / BK - 1) {
            int k0 = (t + 1) * BK;
            #pragma unroll
            for (int it = 0; it < 2; it++) {
                int grow = block_row + a_r + it * 64;
                pa[it] = (grow < M) ? *(const float4*)&A[(size_t)grow * K + k0 + a_c]
                                    : make_float4(0.f, 0.f, 0.f, 0.f);
                pb[it] = *(const float4*)&B[(size_t)(k0 + b_r + it * 8) * BN + b_c];
            }
        }
        __syncthreads();

        #pragma unroll
        for (int k = 0; k < BK; k++) {
            unsigned long long ra2[TM], rb2[TN / 2];
            #pragma unroll
            for (int i = 0; i < TM; i++) {
                float a = As[k][ty * TM + i];
                ra2[i] = pack2(a, a);
            }
            #pragma unroll
            for (int j = 0; j < TN / 2; j++)
                rb2[j] = *(const unsigned long long*)&Bs[k][tx * TN + 2 * j];
            #pragma unroll
            for (int i = 0; i < TM; i++)
                #pragma unroll
                for (int j = 0; j < TN / 2; j++)
                    fma2(acc2[i][j], ra2[i], rb2[j]);
        }
    }

    #pragma unroll
    for (int i = 0; i < TM; i++) {
        int grow = block_row + ty * TM + i;
        if (grow < M) {
            __half2 h[4];
            #pragma unroll
            for (int j = 0; j < 4; j++)
                h[j] = __floats2half2_rn(lo32(acc2[i][j]), hi32(acc2[i][j]));
            *(uint4*)&g_h1[(size_t)grow * BN + tx * TN] = *(uint4*)h;
        }
    }
}

__global__ void __launch_bounds__(256) sgemm2(
    const float* __restrict__ B, int M)
{
    constexpr int BM = 128, BN = 64, BK = 16, K = 128, TM = 8, TN = 4;
    __shared__ float As[BK][BM];
    __shared__ float Bs[BK][BN];

    const int tid = threadIdx.x;
    const int block_row = blockIdx.x * BM;
    const int tx = tid % (BN / TN);
    const int ty = tid / (BN / TN);

    unsigned long long acc2[TM][TN / 2];
    #pragma unroll
    for (int i = 0; i < TM; i++)
        #pragma unroll
        for (int j = 0; j < TN / 2; j++) acc2[i][j] = 0ull;

    const int a_r = tid / 4;
    const int a_c = (tid % 4) * 4;
    const int b_r = tid / 16;
    const int b_c = (tid % 16) * 4;

    float4 pa[2], pb;
    #pragma unroll
    for (int it = 0; it < 2; it++) {
        int grow = block_row + a_r + it * 64;
        pa[it] = (grow < M) ? *(const float4*)&g_a1[(size_t)grow * K + a_c]
                            : make_float4(0.f, 0.f, 0.f, 0.f);
    }
    pb = *(const float4*)&B[(size_t)b_r * BN + b_c];

    for (int t = 0; t < K / BK; t++) {
        __syncthreads();
        #pragma unroll
        for (int it = 0; it < 2; it++) {
            int r = a_r + it * 64;
            As[a_c + 0][r] = pa[it].x;
            As[a_c + 1][r] = pa[it].y;
            As[a_c + 2][r] = pa[it].z;
            As[a_c + 3][r] = pa[it].w;
        }
        *(float4*)&Bs[b_r][b_c] = pb;
        if (t < K / BK - 1) {
            int k0 = (t + 1) * BK;
            #pragma unroll
            for (int it = 0; it < 2; it++) {
                int grow = block_row + a_r + it * 64;
                pa[it] = (grow < M) ? *(const float4*)&g_a1[(size_t)grow * K + k0 + a_c]
                                    : make_float4(0.f, 0.f, 0.f, 0.f);
            }
            pb = *(const float4*)&B[(size_t)(k0 + b_r) * BN + b_c];
        }
        __syncthreads();

        #pragma unroll
        for (int k = 0; k < BK; k++) {
            unsigned long long ra2[TM], rb2[TN / 2];
            #pragma unroll
            for (int i = 0; i < TM; i++) {
                float a = As[k][ty * TM + i];
                ra2[i] = pack2(a, a);
            }
            #pragma unroll
            for (int j = 0; j < TN / 2; j++)
                rb2[j] = *(const unsigned long long*)&Bs[k][tx * TN + 2 * j];
            #pragma unroll
            for (int i = 0; i < TM; i++)
                #pragma unroll
                for (int j = 0; j < TN / 2; j++)
                    fma2(acc2[i][j], ra2[i], rb2[j]);
        }
    }

    #pragma unroll
    for (int i = 0; i < TM; i++) {
        int grow = block_row + ty * TM + i;
        if (grow < M) {
            __half2 h[2];
            h[0] = __floats2half2_rn(lo32(acc2[i][0]), hi32(acc2[i][0]));
            h[1] = __floats2half2_rn(lo32(acc2[i][1]), hi32(acc2[i][1]));
            *(uint2*)&g_h2[(size_t)grow * BN + tx * TN] = *(uint2*)h;
        }
    }
}

// ---------------------------------------------------------------------------
// Segment aggregation: warp per node; fp16 gathers, fp32 accumulate.
__global__ void __launch_bounds__(256) agg128_relu(
    const float* __restrict__ bias)
{
    int gw = (blockIdx.x * blockDim.x + threadIdx.x) >> 5;
    int lane = threadIdx.x & 31;
    if (gw >= NN) return;
    int beg = g_off[gw], end = g_off[gw + 1];
    int c4 = lane * 4;

    float4 acc = make_float4(0.f, 0.f, 0.f, 0.f);
    int idx = beg;
    for (; idx + 4 <= end; idx += 4) {
        int s0 = g_src[idx + 0];
        int s1 = g_src[idx + 1];
        int s2 = g_src[idx + 2];
        int s3 = g_src[idx + 3];
        float n0 = g_dis[s0], n1 = g_dis[s1], n2 = g_dis[s2], n3 = g_dis[s3];
        uint2 u0 = *(const uint2*)(g_h1 + (size_t)s0 * 128 + c4);
        uint2 u1 = *(const uint2*)(g_h1 + (size_t)s1 * 128 + c4);
        uint2 u2 = *(const uint2*)(g_h1 + (size_t)s2 * 128 + c4);
        uint2 u3 = *(const uint2*)(g_h1 + (size_t)s3 * 128 + c4);
        float4 v0 = h4_to_f4(u0);
        float4 v1 = h4_to_f4(u1);
        float4 v2 = h4_to_f4(u2);
        float4 v3 = h4_to_f4(u3);
        acc.x = fmaf(n0, v0.x, acc.x); acc.y = fmaf(n0, v0.y, acc.y);
        acc.z = fmaf(n0, v0.z, acc.z); acc.w = fmaf(n0, v0.w, acc.w);
        acc.x = fmaf(n1, v1.x, acc.x); acc.y = fmaf(n1, v1.y, acc.y);
        acc.z = fmaf(n1, v1.z, acc.z); acc.w = fmaf(n1, v1.w, acc.w);
        acc.x = fmaf(n2, v2.x, acc.x); acc.y = fmaf(n2, v2.y, acc.y);
        acc.z = fmaf(n2, v2.z, acc.z); acc.w = fmaf(n2, v2.w, acc.w);
        acc.x = fmaf(n3, v3.x, acc.x); acc.y = fmaf(n3, v3.y, acc.y);
        acc.z = fmaf(n3, v3.z, acc.z); acc.w = fmaf(n3, v3.w, acc.w);
    }
    for (; idx < end; idx++) {
        int s = g_src[idx];
        float n = g_dis[s];
        float4 v = h4_to_f4(*(const uint2*)(g_h1 + (size_t)s * 128 + c4));
        acc.x = fmaf(n, v.x, acc.x); acc.y = fmaf(n, v.y, acc.y);
        acc.z = fmaf(n, v.z, acc.z); acc.w = fmaf(n, v.w, acc.w);
    }
    float dd = g_dis[gw];
    float4 bb = *(const float4*)(bias + c4);
    acc.x = fmaxf(fmaf(dd, acc.x, bb.x), 0.f);
    acc.y = fmaxf(fmaf(dd, acc.y, bb.y), 0.f);
    acc.z = fmaxf(fmaf(dd, acc.z, bb.z), 0.f);
    acc.w = fmaxf(fmaf(dd, acc.w, bb.w), 0.f);
    *(float4*)(g_a1 + (size_t)gw * 128 + c4) = acc;
}

// last kernel: also zeroes g_deg/g_cnt for the next launch
__global__ void __launch_bounds__(256) agg64_out(
    const float* __restrict__ bias, float* __restrict__ OUT)
{
    int gw = (blockIdx.x * blockDim.x + threadIdx.x) >> 5;
    int lane = threadIdx.x & 31;
    if (gw >= NN) return;
    int beg = g_off[gw], end = g_off[gw + 1];
    int c2 = lane * 2;

    float2 acc = make_float2(0.f, 0.f);
    int idx = beg;
    for (; idx + 4 <= end; idx += 4) {
        int s0 = g_src[idx + 0];
        int s1 = g_src[idx + 1];
        int s2 = g_src[idx + 2];
        int s3 = g_src[idx + 3];
        float n0 = g_dis[s0], n1 = g_dis[s1], n2 = g_dis[s2], n3 = g_dis[s3];
        float2 v0 = h2_to_f2(*(const unsigned*)(g_h2 + (size_t)s0 * 64 + c2));
        float2 v1 = h2_to_f2(*(const unsigned*)(g_h2 + (size_t)s1 * 64 + c2));
        float2 v2 = h2_to_f2(*(const unsigned*)(g_h2 + (size_t)s2 * 64 + c2));
        float2 v3 = h2_to_f2(*(const unsigned*)(g_h2 + (size_t)s3 * 64 + c2));
        acc.x = fmaf(n0, v0.x, acc.x); acc.y = fmaf(n0, v0.y, acc.y);
        acc.x = fmaf(n1, v1.x, acc.x); acc.y = fmaf(n1, v1.y, acc.y);
        acc.x = fmaf(n2, v2.x, acc.x); acc.y = fmaf(n2, v2.y, acc.y);
        acc.x = fmaf(n3, v3.x, acc.x); acc.y = fmaf(n3, v3.y, acc.y);
    }
    for (; idx < end; idx++) {
        int s = g_src[idx];
        float n = g_dis[s];
        float2 v = h2_to_f2(*(const unsigned*)(g_h2 + (size_t)s * 64 + c2));
        acc.x = fmaf(n, v.x, acc.x); acc.y = fmaf(n, v.y, acc.y);
    }
    float dd = g_dis[gw];
    float2 bb = *(const float2*)(bias + c2);
    acc.x = fmaf(dd, acc.x, bb.x);
    acc.y = fmaf(dd, acc.y, bb.y);
    *(float2*)(OUT + (size_t)gw * 64 + c2) = acc;

    if (lane == 0) { g_deg[gw] = 0; g_cnt[gw] = 0; }
}

// ---------------------------------------------------------------------------
extern "C" void kernel_launch(void* const* d_in, const int* in_sizes, int n_in,
                              void* d_out, int out_size) {
    const float* x  = (const float*)d_in[0];
    const int*   ei = (const int*)d_in[1];
    const float* W1 = (const float*)d_in[2];
    const float* b1 = (const float*)d_in[3];
    const float* W2 = (const float*)d_in[4];
    const float* b2 = (const float*)d_in[5];
    float*       out = (float*)d_out;

    static cudaStream_t s2 = nullptr;
    static cudaEvent_t evFork = nullptr, evJoin = nullptr;
    if (s2 == nullptr) {
        cudaStreamCreateWithFlags(&s2, cudaStreamNonBlocking);
        cudaEventCreateWithFlags(&evFork, cudaEventDisableTiming);
        cudaEventCreateWithFlags(&evJoin, cudaEventDisableTiming);
    }

    const int TB = 256;

    // fork: sgemm1 (x@W1, independent of graph prep) on s2
    cudaEventRecord(evFork, 0);
    cudaStreamWaitEvent(s2, evFork, 0);
    sgemm1<<<(NN + 127) / 128, 256, 0, s2>>>(x, W1, NN);
    cudaEventRecord(evJoin, s2);

    // graph prep on main stream
    degree_kernel<<<(NE / 2 + TB - 1) / TB, TB>>>(ei);
    scan_p1p2<<<NBLK, 256>>>();
    scan_p3<<<NBLK, 256>>>();
    scatter_kernel<<<(ET + TB - 1) / TB, TB>>>(ei);

    // join, then rest of the pipeline
    cudaStreamWaitEvent(0, evJoin, 0);
    agg128_relu<<<(NN * 32 + TB - 1) / TB, TB>>>(b1);
    sgemm2<<<(NN + 127) / 128, 256>>>(W2, NN);
    agg64_out<<<(NN * 32 + TB - 1) / TB, TB>>>(b2, out);
}

// round 12
// speedup vs baseline: 2.1747x; 1.2384x over previous
#include <cuda_runtime.h>
#include <cuda_bf16.h>
#include <cuda_fp16.h>
#include <mma.h>

using namespace nvcuda;

// 2-layer GCN. Ahat = D^-1/2 (A+I) D^-1/2, factored:
//   agg(h)[d] = dis[d] * sum_{s in N(d)} dis[s] * h[s]
// int32 edges; counting-sort by dst; warp-per-node segment aggregation with
// fp16 gathers. GEMMs run on tensor cores (fp16 WMMA, fp32 accumulate),
// operands converted fp32->fp16 in the smem load path.

#define NN 50000
#define NE 800000
#define ET (NN + NE)
#define FIN 128
#define D1  128
#define NCLS 64
#define NBLK ((NN + 255) / 256)

// ---- device scratch (static, no allocation) ----
__device__ __half g_h1[NN * D1];     // fp16 x@W1
__device__ float  g_a1[NN * D1];     // fp32 relu(agg)
__device__ __half g_h2[NN * NCLS];   // fp16 a1@W2
__device__ int    g_deg[NN];         // zeroed by tail of previous launch
__device__ float  g_dis[NN];
__device__ int    g_off[NN + 1];
__device__ int    g_cnt[NN];         // zeroed by tail of previous launch
__device__ int    g_src[ET];
__device__ int    g_bsum[NBLK];
__device__ int    g_boff[NBLK];
__device__ int    g_tick;            // reset by last scan block

__device__ __forceinline__ float4 h4_to_f4(uint2 u) {
    __half2 a = *reinterpret_cast<__half2*>(&u.x);
    __half2 b = *reinterpret_cast<__half2*>(&u.y);
    float2 fa = __half22float2(a), fb = __half22float2(b);
    return make_float4(fa.x, fa.y, fb.x, fb.y);
}
__device__ __forceinline__ float2 h2_to_f2(unsigned u) {
    __half2 a = *reinterpret_cast<__half2*>(&u);
    return __half22float2(a);
}

// ---------------------------------------------------------------------------
__global__ void degree_kernel(const int* __restrict__ ei) {
    int e = blockIdx.x * blockDim.x + threadIdx.x;
    if (e < NE / 2) {
        int2 d2 = ((const int2*)(ei + NE))[e];
        atomicAdd(&g_deg[d2.x], 1);
        atomicAdd(&g_deg[d2.y], 1);
    }
}

// fused phase1+2: per-block reduce of deg+1; last block scans block sums.
__global__ void __launch_bounds__(256) scan_p1p2() {
    __shared__ int wsum[8];
    __shared__ int amLast;
    int tid = threadIdx.x, lane = tid & 31, w = tid >> 5;
    int i = blockIdx.x * 256 + tid;
    int v = (i < NN) ? g_deg[i] + 1 : 0;
    int x = v;
    #pragma unroll
    for (int d = 16; d > 0; d >>= 1) x += __shfl_down_sync(0xffffffffu, x, d);
    if (lane == 0) wsum[w] = x;
    __syncthreads();
    if (tid < 8) {
        int y = wsum[tid];
        #pragma unroll
        for (int d = 4; d > 0; d >>= 1) y += __shfl_down_sync(0xffu, y, d);
        if (tid == 0) g_bsum[blockIdx.x] = y;
    }
    if (tid == 0) {
        __threadfence();
        amLast = (atomicAdd(&g_tick, 1) == NBLK - 1) ? 1 : 0;
    }
    __syncthreads();
    if (amLast) {
        int bv = (tid < NBLK) ? g_bsum[tid] : 0;
        int bx = bv;
        #pragma unroll
        for (int d = 1; d < 32; d <<= 1) {
            int t = __shfl_up_sync(0xffffffffu, bx, d);
            if (lane >= d) bx += t;
        }
        if (lane == 31) wsum[w] = bx;
        __syncthreads();
        if (w == 0 && lane < 8) {
            int y = wsum[lane];
            #pragma unroll
            for (int d = 1; d < 8; d <<= 1) {
                int t = __shfl_up_sync(0xffu, y, d);
                if (lane >= d) y += t;
            }
            wsum[lane] = y;
        }
        __syncthreads();
        int excl = bx - bv + (w > 0 ? wsum[w - 1] : 0);
        if (tid < NBLK) g_boff[tid] = excl;
        if (tid == NBLK - 1) g_off[NN] = excl + bv;   // == ET
        if (tid == 0) g_tick = 0;
    }
}

__global__ void __launch_bounds__(256) scan_p3() {
    __shared__ int wsum[8];
    int tid = threadIdx.x, lane = tid & 31, w = tid >> 5;
    int i = blockIdx.x * 256 + tid;
    int v = 0;
    if (i < NN) {
        v = g_deg[i] + 1;
        g_dis[i] = rsqrtf((float)v);
    }
    int x = v;
    #pragma unroll
    for (int d = 1; d < 32; d <<= 1) {
        int t = __shfl_up_sync(0xffffffffu, x, d);
        if (lane >= d) x += t;
    }
    if (lane == 31) wsum[w] = x;
    __syncthreads();
    if (w == 0 && lane < 8) {
        int y = wsum[lane];
        #pragma unroll
        for (int d = 1; d < 8; d <<= 1) {
            int t = __shfl_up_sync(0xffu, y, d);
            if (lane >= d) y += t;
        }
        wsum[lane] = y;
    }
    __syncthreads();
    int excl = x - v + (w > 0 ? wsum[w - 1] : 0) + g_boff[blockIdx.x];
    if (i < NN) g_off[i] = excl;
}

__global__ void scatter_kernel(const int* __restrict__ ei) {
    int e = blockIdx.x * blockDim.x + threadIdx.x;
    if (e >= ET) return;
    int s, d;
    if (e < NE) { s = ei[e]; d = ei[NE + e]; }
    else        { s = d = e - NE; }
    int pos = g_off[d] + atomicAdd(&g_cnt[d], 1);
    g_src[pos] = s;
}

// ---------------------------------------------------------------------------
// helpers: fp32x4 -> half4 (uint2)
__device__ __forceinline__ uint2 f4_to_h4(float4 v) {
    __half2 h0 = __floats2half2_rn(v.x, v.y);
    __half2 h1 = __floats2half2_rn(v.z, v.w);
    uint2 r;
    r.x = *reinterpret_cast<unsigned*>(&h0);
    r.y = *reinterpret_cast<unsigned*>(&h1);
    return r;
}

// ---------------------------------------------------------------------------
// Tensor-core GEMM 1: g_h1[M,128] = fp16( A[M,128] @ B[128,128] )
// BM=128, BN=128, BK=32; 8 warps (4 M x 2 N), warp tile 32x64.
__global__ void __launch_bounds__(256) wgemm1(
    const float* __restrict__ A, const float* __restrict__ B, int M)
{
    constexpr int LDA = 40, LDB = 136;
    __shared__ __half As[128 * LDA];
    __shared__ __half Bs[32 * LDB];
    __shared__ float  cst[8][256];

    const int tid = threadIdx.x;
    const int wid = tid >> 5;
    const int lane = tid & 31;
    const int block_row = blockIdx.x * 128;
    const int warpM = wid & 3;          // 0..3 -> 32-row tile
    const int warpN = wid >> 2;         // 0..1 -> 64-col tile

    wmma::fragment<wmma::accumulator, 16, 16, 16, float> cf[2][4];
    #pragma unroll
    for (int i = 0; i < 2; i++)
        #pragma unroll
        for (int j = 0; j < 4; j++) wmma::fill_fragment(cf[i][j], 0.f);

    const int a_row = tid >> 1;                 // 0..127
    const int a_cg  = (tid & 1) * 16;           // 0,16
    const int b_row = tid >> 3;                 // 0..31
    const int b_cg  = (tid & 7) * 16;           // 0..112

    for (int t = 0; t < 4; t++) {               // K = 4 * 32
        int k0 = t * 32;
        // load + convert A tile 128x32
        {
            int grow = block_row + a_row;
            float4 v0 = make_float4(0.f,0.f,0.f,0.f), v1 = v0, v2 = v0, v3 = v0;
            if (grow < M) {
                const float4* p = (const float4*)&A[(size_t)grow * 128 + k0 + a_cg];
                v0 = p[0]; v1 = p[1]; v2 = p[2]; v3 = p[3];
            }
            uint2* dst = (uint2*)&As[a_row * LDA + a_cg];
            dst[0] = f4_to_h4(v0); dst[1] = f4_to_h4(v1);
            dst[2] = f4_to_h4(v2); dst[3] = f4_to_h4(v3);
        }
        // load + convert B tile 32x128
        {
            const float4* p = (const float4*)&B[(size_t)(k0 + b_row) * 128 + b_cg];
            float4 v0 = p[0], v1 = p[1], v2 = p[2], v3 = p[3];
            uint2* dst = (uint2*)&Bs[b_row * LDB + b_cg];
            dst[0] = f4_to_h4(v0); dst[1] = f4_to_h4(v1);
            dst[2] = f4_to_h4(v2); dst[3] = f4_to_h4(v3);
        }
        __syncthreads();

        #pragma unroll
        for (int ks = 0; ks < 2; ks++) {
            wmma::fragment<wmma::matrix_a, 16, 16, 16, __half, wmma::row_major> af[2];
            wmma::fragment<wmma::matrix_b, 16, 16, 16, __half, wmma::row_major> bf[4];
            #pragma unroll
            for (int i = 0; i < 2; i++)
                wmma::load_matrix_sync(af[i], &As[(warpM * 32 + i * 16) * LDA + ks * 16], LDA);
            #pragma unroll
            for (int j = 0; j < 4; j++)
                wmma::load_matrix_sync(bf[j], &Bs[(ks * 16) * LDB + warpN * 64 + j * 16], LDB);
            #pragma unroll
            for (int i = 0; i < 2; i++)
                #pragma unroll
                for (int j = 0; j < 4; j++)
                    wmma::mma_sync(cf[i][j], af[i], bf[j], cf[i][j]);
        }
        __syncthreads();
    }

    // epilogue: per-warp smem staging, pack fp16, uint4 stores
    #pragma unroll
    for (int i = 0; i < 2; i++) {
        #pragma unroll
        for (int j = 0; j < 4; j++) {
            wmma::store_matrix_sync(cst[wid], cf[i][j], 16, wmma::mem_row_major);
            __syncwarp();
            int r  = lane >> 1;
            int co = (lane & 1) * 8;
            int grow = block_row + warpM * 32 + i * 16 + r;
            if (grow < M) {
                const float* s = &cst[wid][r * 16 + co];
                __half2 h[4];
                h[0] = __floats2half2_rn(s[0], s[1]);
                h[1] = __floats2half2_rn(s[2], s[3]);
                h[2] = __floats2half2_rn(s[4], s[5]);
                h[3] = __floats2half2_rn(s[6], s[7]);
                *(uint4*)&g_h1[(size_t)grow * 128 + warpN * 64 + j * 16 + co] = *(uint4*)h;
            }
            __syncwarp();
        }
    }
}

// Tensor-core GEMM 2: g_h2[M,64] = fp16( g_a1[M,128] @ B[128,64] )
// BM=128, BN=64, BK=32; 8 warps (4 M x 2 N), warp tile 32x32.
__global__ void __launch_bounds__(256) wgemm2(
    const float* __restrict__ B, int M)
{
    constexpr int LDA = 40, LDB = 72;
    __shared__ __half As[128 * LDA];
    __shared__ __half Bs[32 * LDB];
    __shared__ float  cst[8][256];

    const int tid = threadIdx.x;
    const int wid = tid >> 5;
    const int lane = tid & 31;
    const int block_row = blockIdx.x * 128;
    const int warpM = wid & 3;
    const int warpN = wid >> 2;

    wmma::fragment<wmma::accumulator, 16, 16, 16, float> cf[2][2];
    #pragma unroll
    for (int i = 0; i < 2; i++)
        #pragma unroll
        for (int j = 0; j < 2; j++) wmma::fill_fragment(cf[i][j], 0.f);

    const int a_row = tid >> 1;
    const int a_cg  = (tid & 1) * 16;
    const int b_row = tid >> 2;                 // 0..63 -> but only 32 rows
    const int b_cg  = (tid & 3) * 16;

    for (int t = 0; t < 4; t++) {
        int k0 = t * 32;
        {
            int grow = block_row + a_row;
            float4 v0 = make_float4(0.f,0.f,0.f,0.f), v1 = v0, v2 = v0, v3 = v0;
            if (grow < M) {
                const float4* p = (const float4*)&g_a1[(size_t)grow * 128 + k0 + a_cg];
                v0 = p[0]; v1 = p[1]; v2 = p[2]; v3 = p[3];
            }
            uint2* dst = (uint2*)&As[a_row * LDA + a_cg];
            dst[0] = f4_to_h4(v0); dst[1] = f4_to_h4(v1);
            dst[2] = f4_to_h4(v2); dst[3] = f4_to_h4(v3);
        }
        if (b_row < 32) {                       // 32x64 tile, half the threads
            const float4* p = (const float4*)&B[(size_t)(k0 + b_row) * 64 + b_cg];
            float4 v0 = p[0], v1 = p[1], v2 = p[2], v3 = p[3];
            uint2* dst = (uint2*)&Bs[b_row * LDB + b_cg];
            dst[0] = f4_to_h4(v0); dst[1] = f4_to_h4(v1);
            dst[2] = f4_to_h4(v2); dst[3] = f4_to_h4(v3);
        }
        __syncthreads();

        #pragma unroll
        for (int ks = 0; ks < 2; ks++) {
            wmma::fragment<wmma::matrix_a, 16, 16, 16, __half, wmma::row_major> af[2];
            wmma::fragment<wmma::matrix_b, 16, 16, 16, __half, wmma::row_major> bf[2];
            #pragma unroll
            for (int i = 0; i < 2; i++)
                wmma::load_matrix_sync(af[i], &As[(warpM * 32 + i * 16) * LDA + ks * 16], LDA);
            #pragma unroll
            for (int j = 0; j < 2; j++)
                wmma::load_matrix_sync(bf[j], &Bs[(ks * 16) * LDB + warpN * 32 + j * 16], LDB);
            #pragma unroll
            for (int i = 0; i < 2; i++)
                #pragma unroll
                for (int j = 0; j < 2; j++)
                    wmma::mma_sync(cf[i][j], af[i], bf[j], cf[i][j]);
        }
        __syncthreads();
    }

    #pragma unroll
    for (int i = 0; i < 2; i++) {
        #pragma unroll
        for (int j = 0; j < 2; j++) {
            wmma::store_matrix_sync(cst[wid], cf[i][j], 16, wmma::mem_row_major);
            __syncwarp();
            int r  = lane >> 1;
            int co = (lane & 1) * 8;
            int grow = block_row + warpM * 32 + i * 16 + r;
            if (grow < M) {
                const float* s = &cst[wid][r * 16 + co];
                __half2 h[4];
                h[0] = __floats2half2_rn(s[0], s[1]);
                h[1] = __floats2half2_rn(s[2], s[3]);
                h[2] = __floats2half2_rn(s[4], s[5]);
                h[3] = __floats2half2_rn(s[6], s[7]);
                *(uint4*)&g_h2[(size_t)grow * 64 + warpN * 32 + j * 16 + co] = *(uint4*)h;
            }
            __syncwarp();
        }
    }
}

// ---------------------------------------------------------------------------
// Segment aggregation: warp per node; fp16 gathers, fp32 accumulate.
__global__ void __launch_bounds__(256) agg128_relu(
    const float* __restrict__ bias)
{
    int gw = (blockIdx.x * blockDim.x + threadIdx.x) >> 5;
    int lane = threadIdx.x & 31;
    if (gw >= NN) return;
    int beg = g_off[gw], end = g_off[gw + 1];
    int c4 = lane * 4;

    float4 acc = make_float4(0.f, 0.f, 0.f, 0.f);
    int idx = beg;
    for (; idx + 4 <= end; idx += 4) {
        int s0 = g_src[idx + 0];
        int s1 = g_src[idx + 1];
        int s2 = g_src[idx + 2];
        int s3 = g_src[idx + 3];
        float n0 = g_dis[s0], n1 = g_dis[s1], n2 = g_dis[s2], n3 = g_dis[s3];
        uint2 u0 = *(const uint2*)(g_h1 + (size_t)s0 * 128 + c4);
        uint2 u1 = *(const uint2*)(g_h1 + (size_t)s1 * 128 + c4);
        uint2 u2 = *(const uint2*)(g_h1 + (size_t)s2 * 128 + c4);
        uint2 u3 = *(const uint2*)(g_h1 + (size_t)s3 * 128 + c4);
        float4 v0 = h4_to_f4(u0);
        float4 v1 = h4_to_f4(u1);
        float4 v2 = h4_to_f4(u2);
        float4 v3 = h4_to_f4(u3);
        acc.x = fmaf(n0, v0.x, acc.x); acc.y = fmaf(n0, v0.y, acc.y);
        acc.z = fmaf(n0, v0.z, acc.z); acc.w = fmaf(n0, v0.w, acc.w);
        acc.x = fmaf(n1, v1.x, acc.x); acc.y = fmaf(n1, v1.y, acc.y);
        acc.z = fmaf(n1, v1.z, acc.z); acc.w = fmaf(n1, v1.w, acc.w);
        acc.x = fmaf(n2, v2.x, acc.x); acc.y = fmaf(n2, v2.y, acc.y);
        acc.z = fmaf(n2, v2.z, acc.z); acc.w = fmaf(n2, v2.w, acc.w);
        acc.x = fmaf(n3, v3.x, acc.x); acc.y = fmaf(n3, v3.y, acc.y);
        acc.z = fmaf(n3, v3.z, acc.z); acc.w = fmaf(n3, v3.w, acc.w);
    }
    for (; idx < end; idx++) {
        int s = g_src[idx];
        float n = g_dis[s];
        float4 v = h4_to_f4(*(const uint2*)(g_h1 + (size_t)s * 128 + c4));
        acc.x = fmaf(n, v.x, acc.x); acc.y = fmaf(n, v.y, acc.y);
        acc.z = fmaf(n, v.z, acc.z); acc.w = fmaf(n, v.w, acc.w);
    }
    float dd = g_dis[gw];
    float4 bb = *(const float4*)(bias + c4);
    acc.x = fmaxf(fmaf(dd, acc.x, bb.x), 0.f);
    acc.y = fmaxf(fmaf(dd, acc.y, bb.y), 0.f);
    acc.z = fmaxf(fmaf(dd, acc.z, bb.z), 0.f);
    acc.w = fmaxf(fmaf(dd, acc.w, bb.w), 0.f);
    *(float4*)(g_a1 + (size_t)gw * 128 + c4) = acc;
}

// last kernel: also zeroes g_deg/g_cnt for the next launch
__global__ void __launch_bounds__(256) agg64_out(
    const float* __restrict__ bias, float* __restrict__ OUT)
{
    int gw = (blockIdx.x * blockDim.x + threadIdx.x) >> 5;
    int lane = threadIdx.x & 31;
    if (gw >= NN) return;
    int beg = g_off[gw], end = g_off[gw + 1];
    int c2 = lane * 2;

    float2 acc = make_float2(0.f, 0.f);
    int idx = beg;
    for (; idx + 4 <= end; idx += 4) {
        int s0 = g_src[idx + 0];
        int s1 = g_src[idx + 1];
        int s2 = g_src[idx + 2];
        int s3 = g_src[idx + 3];
        float n0 = g_dis[s0], n1 = g_dis[s1], n2 = g_dis[s2], n3 = g_dis[s3];
        float2 v0 = h2_to_f2(*(const unsigned*)(g_h2 + (size_t)s0 * 64 + c2));
        float2 v1 = h2_to_f2(*(const unsigned*)(g_h2 + (size_t)s1 * 64 + c2));
        float2 v2 = h2_to_f2(*(const unsigned*)(g_h2 + (size_t)s2 * 64 + c2));
        float2 v3 = h2_to_f2(*(const unsigned*)(g_h2 + (size_t)s3 * 64 + c2));
        acc.x = fmaf(n0, v0.x, acc.x); acc.y = fmaf(n0, v0.y, acc.y);
        acc.x = fmaf(n1, v1.x, acc.x); acc.y = fmaf(n1, v1.y, acc.y);
        acc.x = fmaf(n2, v2.x, acc.x); acc.y = fmaf(n2, v2.y, acc.y);
        acc.x = fmaf(n3, v3.x, acc.x); acc.y = fmaf(n3, v3.y, acc.y);
    }
    for (; idx < end; idx++) {
        int s = g_src[idx];
        float n = g_dis[s];
        float2 v = h2_to_f2(*(const unsigned*)(g_h2 + (size_t)s * 64 + c2));
        acc.x = fmaf(n, v.x, acc.x); acc.y = fmaf(n, v.y, acc.y);
    }
    float dd = g_dis[gw];
    float2 bb = *(const float2*)(bias + c2);
    acc.x = fmaf(dd, acc.x, bb.x);
    acc.y = fmaf(dd, acc.y, bb.y);
    *(float2*)(OUT + (size_t)gw * 64 + c2) = acc;

    if (lane == 0) { g_deg[gw] = 0; g_cnt[gw] = 0; }
}

// ---------------------------------------------------------------------------
extern "C" void kernel_launch(void* const* d_in, const int* in_sizes, int n_in,
                              void* d_out, int out_size) {
    const float* x  = (const float*)d_in[0];
    const int*   ei = (const int*)d_in[1];
    const float* W1 = (const float*)d_in[2];
    const float* b1 = (const float*)d_in[3];
    const float* W2 = (const float*)d_in[4];
    const float* b2 = (const float*)d_in[5];
    float*       out = (float*)d_out;

    static cudaStream_t s2 = nullptr;
    static cudaEvent_t evFork = nullptr, evJoin = nullptr;
    if (s2 == nullptr) {
        cudaStreamCreateWithFlags(&s2, cudaStreamNonBlocking);
        cudaEventCreateWithFlags(&evFork, cudaEventDisableTiming);
        cudaEventCreateWithFlags(&evJoin, cudaEventDisableTiming);
    }

    const int TB = 256;

    // fork: wgemm1 (x@W1, independent of graph prep) on s2
    cudaEventRecord(evFork, 0);
    cudaStreamWaitEvent(s2, evFork, 0);
    wgemm1<<<(NN + 127) / 128, 256, 0, s2>>>(x, W1, NN);
    cudaEventRecord(evJoin, s2);

    // graph prep on main stream
    degree_kernel<<<(NE / 2 + TB - 1) / TB, TB>>>(ei);
    scan_p1p2<<<NBLK, 256>>>();
    scan_p3<<<NBLK, 256>>>();
    scatter_kernel<<<(ET + TB - 1) / TB, TB>>>(ei);

    // join, then rest of the pipeline
    cudaStreamWaitEvent(0, evJoin, 0);
    agg128_relu<<<(NN * 32 + TB - 1) / TB, TB>>>(b1);
    wgemm2<<<(NN + 127) / 128, 256>>>(W2, NN);
    agg64_out<<<(NN * 32 + TB - 1) / TB, TB>>>(b2, out);
}